// round 14
// baseline (speedup 1.0000x reference)
#include <cuda_runtime.h>
#include <cuda_bf16.h>
#include <math.h>
#include <stdint.h>

#define B_    2
#define N_    1024
#define D_    256
#define H_    8
#define DH_   32
#define K_    4
#define IN_   1024
#define V_    32000
#define CK_   3
#define MAXL_ 8
#define TRUNC_ 4
#define BN_   (B_ * N_)

// ---------------- fp32 scratch ----------------
__device__ float g_X [BN_ * D_];
__device__ float g_Q [BN_ * D_];
__device__ float g_gu[BN_ * 2 * IN_];
__device__ float g_qn[2][BN_ * D_];
__device__ float g_hd[2][BN_];

// ---------------- activation split planes (bf16 hi/lo) ----------------
__device__ __align__(16) __nv_bfloat16 g_hc_h [BN_ * D_],     g_hc_l [BN_ * D_];
__device__ __align__(16) __nv_bfloat16 g_qkv_h[BN_ * 3 * D_], g_qkv_l[BN_ * 3 * D_];
__device__ __align__(16) __nv_bfloat16 g_cmv_h[BN_ * D_],     g_cmv_l[BN_ * D_];
__device__ __align__(16) __nv_bfloat16 g_hn_h [BN_ * D_],     g_hn_l [BN_ * D_];
__device__ __align__(16) __nv_bfloat16 g_hc2_h[BN_ * IN_],    g_hc2_l[BN_ * IN_];
__device__ __align__(16) __nv_bfloat16 g_qn_h [2][BN_ * D_],  g_qn_l [2][BN_ * D_];

// ---------------- transposed split weights [n][k] (bf16 hi/lo) --------
__device__ __align__(16) __nv_bfloat16 g_wq_h [K_ * D_ * D_],      g_wq_l [K_ * D_ * D_];
__device__ __align__(16) __nv_bfloat16 g_wk_h [K_ * D_ * D_],      g_wk_l [K_ * D_ * D_];
__device__ __align__(16) __nv_bfloat16 g_wv_h [K_ * D_ * D_],      g_wv_l [K_ * D_ * D_];
__device__ __align__(16) __nv_bfloat16 g_wo_h [K_ * D_ * D_],      g_wo_l [K_ * D_ * D_];
__device__ __align__(16) __nv_bfloat16 g_wup_h[K_ * 2 * IN_ * D_], g_wup_l[K_ * 2 * IN_ * D_];
__device__ __align__(16) __nv_bfloat16 g_wd_h [K_ * D_ * IN_],     g_wd_l [K_ * D_ * IN_];

// ---------------- side stream + events ----------------
struct SideCtx {
    cudaStream_t s;
    cudaEvent_t  f, j;
    SideCtx() {
        cudaStreamCreateWithFlags(&s, cudaStreamNonBlocking);
        cudaEventCreateWithFlags(&f, cudaEventDisableTiming);
        cudaEventCreateWithFlags(&j, cudaEventDisableTiming);
    }
};
static SideCtx g_sc;

// ---------------- helpers ----------------
__device__ __forceinline__ void split_bf(float v, __nv_bfloat16& h, __nv_bfloat16& l) {
    h = __float2bfloat16_rn(v);
    l = __float2bfloat16_rn(v - __bfloat162float(h));
}
__device__ __forceinline__ uint32_t pack2f(float a, float b) {
    __nv_bfloat162 t = __floats2bfloat162_rn(a, b);
    return *reinterpret_cast<uint32_t*>(&t);
}
__device__ __forceinline__ uint32_t sptr(const void* p) {
    return (uint32_t)__cvta_generic_to_shared(p);
}
__device__ __forceinline__ void ldsm4(uint32_t* r, uint32_t sa) {
    asm volatile("ldmatrix.sync.aligned.m8n8.x4.shared.b16 {%0,%1,%2,%3}, [%4];"
                 : "=r"(r[0]), "=r"(r[1]), "=r"(r[2]), "=r"(r[3]) : "r"(sa));
}
__device__ __forceinline__ void ldsm4t(uint32_t* r, uint32_t sa) {
    asm volatile("ldmatrix.sync.aligned.m8n8.x4.trans.shared.b16 {%0,%1,%2,%3}, [%4];"
                 : "=r"(r[0]), "=r"(r[1]), "=r"(r[2]), "=r"(r[3]) : "r"(sa));
}
__device__ __forceinline__ void mma16(float* c, const uint32_t* a, uint32_t b0, uint32_t b1) {
    asm volatile("mma.sync.aligned.m16n8k16.row.col.f32.bf16.bf16.f32 "
                 "{%0,%1,%2,%3}, {%4,%5,%6,%7}, {%8,%9}, {%0,%1,%2,%3};"
                 : "+f"(c[0]), "+f"(c[1]), "+f"(c[2]), "+f"(c[3])
                 : "r"(a[0]), "r"(a[1]), "r"(a[2]), "r"(a[3]), "r"(b0), "r"(b1));
}
// tf32 helpers (LM head)
__device__ __forceinline__ uint32_t cvt_tf32(float x) {
    uint32_t h;
    asm("cvt.rna.tf32.f32 %0, %1;" : "=r"(h) : "f"(x));
    return h;
}
__device__ __forceinline__ void mma8(float* c, const uint32_t* a, uint32_t b0, uint32_t b1) {
    asm volatile("mma.sync.aligned.m16n8k8.row.col.f32.tf32.tf32.f32 "
                 "{%0,%1,%2,%3}, {%4,%5,%6,%7}, {%8,%9}, {%0,%1,%2,%3};"
                 : "+f"(c[0]), "+f"(c[1]), "+f"(c[2]), "+f"(c[3])
                 : "r"(a[0]), "r"(a[1]), "r"(a[2]), "r"(a[3]), "r"(b0), "r"(b1));
}
__device__ __forceinline__ float warpReduceSum(float v) {
#pragma unroll
    for (int o = 16; o > 0; o >>= 1) v += __shfl_xor_sync(0xffffffffu, v, o);
    return v;
}
__device__ __forceinline__ float blockReduceSum256(float v) {
    __shared__ float sh[8];
    int lane = threadIdx.x & 31;
    int wid  = threadIdx.x >> 5;
#pragma unroll
    for (int o = 16; o > 0; o >>= 1) v += __shfl_down_sync(0xffffffffu, v, o);
    __syncthreads();
    if (lane == 0) sh[wid] = v;
    __syncthreads();
    float t = 0.f;
#pragma unroll
    for (int i = 0; i < 8; i++) t += sh[i];
    return t;
}

// ---------------- weight transpose + split ----------------
__global__ void tsplit(const float* __restrict__ W, __nv_bfloat16* __restrict__ oh,
                       __nv_bfloat16* __restrict__ ol, int Kd, int Nn)
{
    __shared__ float t[32][33];
    const float* Wz = W + (size_t)blockIdx.z * Kd * Nn;
    __nv_bfloat16* ohz = oh + (size_t)blockIdx.z * Kd * Nn;
    __nv_bfloat16* olz = ol + (size_t)blockIdx.z * Kd * Nn;
    int n0 = blockIdx.x * 32, k0 = blockIdx.y * 32;
    int tx = threadIdx.x, ty = threadIdx.y;
#pragma unroll
    for (int i = 0; i < 4; i++)
        t[ty + i * 8][tx] = Wz[(size_t)(k0 + ty + i * 8) * Nn + n0 + tx];
    __syncthreads();
#pragma unroll
    for (int i = 0; i < 4; i++) {
        int n = ty + i * 8;
        float v = t[tx][n];
        __nv_bfloat16 hh, ll; split_bf(v, hh, ll);
        ohz[(size_t)(n0 + n) * Kd + k0 + tx] = hh;
        olz[(size_t)(n0 + n) * Kd + k0 + tx] = ll;
    }
}

// ---------------- embedding / LN ----------------
__global__ void embed_kernel(const int* __restrict__ ids, const float* __restrict__ emb,
                             const float* __restrict__ pos, float* __restrict__ X) {
    int row = blockIdx.x, d = threadIdx.x;
    int n = row & (N_ - 1);
    X[(size_t)row * D_ + d] = emb[(size_t)ids[row] * D_ + d] + pos[(size_t)n * D_ + d];
}

__global__ void ln_kernel(const float* __restrict__ in, const float* __restrict__ w,
                          const float* __restrict__ b, float* __restrict__ out,
                          float* __restrict__ out2) {
    int row = blockIdx.x, d = threadIdx.x;
    float x  = in[(size_t)row * D_ + d];
    float mu = blockReduceSum256(x) * (1.f / D_);
    float dx = x - mu;
    float var = blockReduceSum256(dx * dx) * (1.f / D_);
    float y = dx * rsqrtf(var + 1e-5f) * w[d] + b[d];
    out[(size_t)row * D_ + d] = y;
    if (out2) out2[(size_t)row * D_ + d] = y;
}

__global__ void __launch_bounds__(256)
ln_split(const float* __restrict__ in, const float* __restrict__ w,
         const float* __restrict__ b, const float* __restrict__ addX,
         __nv_bfloat16* __restrict__ oh, __nv_bfloat16* __restrict__ ol,
         float* __restrict__ ofp) {
    int row  = blockIdx.x * 8 + (threadIdx.x >> 5);
    int lane = threadIdx.x & 31;
    const float* ip = in + (size_t)row * D_;
    float x[8], s = 0.f;
#pragma unroll
    for (int j = 0; j < 8; j++) { x[j] = ip[j * 32 + lane]; s += x[j]; }
    float mu = warpReduceSum(s) * (1.f / D_);
    float v = 0.f;
#pragma unroll
    for (int j = 0; j < 8; j++) { float dx = x[j] - mu; v += dx * dx; }
    float rs = rsqrtf(warpReduceSum(v) * (1.f / D_) + 1e-5f);
#pragma unroll
    for (int j = 0; j < 8; j++) {
        int d = j * 32 + lane;
        float y = (x[j] - mu) * rs * w[d] + b[d];
        if (addX) y += addX[(size_t)row * D_ + d];
        __nv_bfloat16 hh, ll; split_bf(y, hh, ll);
        oh[(size_t)row * D_ + d] = hh;
        ol[(size_t)row * D_ + d] = ll;
        if (ofp) ofp[(size_t)row * D_ + d] = y;
    }
}

// ============================================================================
// gemm_bs (mma.sync bf16x3, 64x64x64, reg double-buffer) — R12 known-good
// ============================================================================
#define GS_PAD  72
#define GS_SMEM (4 * 64 * GS_PAD * 2)

template <int MODE>
__global__ void __launch_bounds__(256)
gemm_bs(const __nv_bfloat16* __restrict__ Agh, const __nv_bfloat16* __restrict__ Agl,
        const __nv_bfloat16* __restrict__ B0h, const __nv_bfloat16* __restrict__ B0l,
        const __nv_bfloat16* __restrict__ B1h, const __nv_bfloat16* __restrict__ B1l,
        const __nv_bfloat16* __restrict__ B2h, const __nv_bfloat16* __restrict__ B2l,
        int Kd, int nblk,
        float* __restrict__ Cf, int ldc,
        __nv_bfloat16* __restrict__ Oh, __nv_bfloat16* __restrict__ Ol, int ldo,
        const float* __restrict__ aux, const float* __restrict__ dts, int kidx)
{
    extern __shared__ __nv_bfloat16 sm[];
    __nv_bfloat16* Ash = sm;
    __nv_bfloat16* Asl = Ash + 64 * GS_PAD;
    __nv_bfloat16* Bsh = Asl + 64 * GS_PAD;
    __nv_bfloat16* Bsl = Bsh + 64 * GS_PAD;

    const int tid  = threadIdx.x;
    const int lane = tid & 31, wid = tid >> 5;
    const int g = lane >> 2, tg = lane & 3;
    const int mi = lane >> 3, ri = lane & 7;
    const int wm = wid & 1, wn = wid >> 1;
    const int which = blockIdx.x / nblk;
    const int bxl   = blockIdx.x - which * nblk;
    const int col0  = bxl * 64;
    const int row0  = blockIdx.y * 64;
    const __nv_bfloat16* Bgh = (which == 0) ? B0h : (which == 1) ? B1h : B2h;
    const __nv_bfloat16* Bgl = (which == 0) ? B0l : (which == 1) ? B1l : B2l;

    const int r0 = tid >> 3;
    const int c0 = (tid & 7) * 8;
    const __nv_bfloat16* sA0 = Agh + (size_t)(row0 + r0) * Kd + c0;
    const __nv_bfloat16* sA1 = Agl + (size_t)(row0 + r0) * Kd + c0;
    const __nv_bfloat16* sB0 = Bgh + (size_t)(col0 + r0) * Kd + c0;
    const __nv_bfloat16* sB1 = Bgl + (size_t)(col0 + r0) * Kd + c0;
    const size_t rstep = (size_t)32 * Kd;

    float acc[2][2][4];
#pragma unroll
    for (int a = 0; a < 2; a++)
#pragma unroll
        for (int b = 0; b < 2; b++)
#pragma unroll
            for (int c = 0; c < 4; c++) acc[a][b][c] = 0.f;

    const int niter = Kd >> 6;
    uint4 pr[8];
    pr[0] = *(const uint4*)(sA0);
    pr[1] = *(const uint4*)(sA0 + rstep);
    pr[2] = *(const uint4*)(sA1);
    pr[3] = *(const uint4*)(sA1 + rstep);
    pr[4] = *(const uint4*)(sB0);
    pr[5] = *(const uint4*)(sB0 + rstep);
    pr[6] = *(const uint4*)(sB1);
    pr[7] = *(const uint4*)(sB1 + rstep);

    for (int it2 = 0; it2 < niter; it2++) {
        __syncthreads();
        *(uint4*)(Ash + r0 * GS_PAD + c0)        = pr[0];
        *(uint4*)(Ash + (r0 + 32) * GS_PAD + c0) = pr[1];
        *(uint4*)(Asl + r0 * GS_PAD + c0)        = pr[2];
        *(uint4*)(Asl + (r0 + 32) * GS_PAD + c0) = pr[3];
        *(uint4*)(Bsh + r0 * GS_PAD + c0)        = pr[4];
        *(uint4*)(Bsh + (r0 + 32) * GS_PAD + c0) = pr[5];
        *(uint4*)(Bsl + r0 * GS_PAD + c0)        = pr[6];
        *(uint4*)(Bsl + (r0 + 32) * GS_PAD + c0) = pr[7];
        __syncthreads();
        if (it2 + 1 < niter) {
            int o = (it2 + 1) * 64;
            pr[0] = *(const uint4*)(sA0 + o);
            pr[1] = *(const uint4*)(sA0 + rstep + o);
            pr[2] = *(const uint4*)(sA1 + o);
            pr[3] = *(const uint4*)(sA1 + rstep + o);
            pr[4] = *(const uint4*)(sB0 + o);
            pr[5] = *(const uint4*)(sB0 + rstep + o);
            pr[6] = *(const uint4*)(sB1 + o);
            pr[7] = *(const uint4*)(sB1 + rstep + o);
        }

#pragma unroll
        for (int ks = 0; ks < 4; ks++) {
            int kb = ks * 16;
            uint32_t ah[2][4], al[2][4];
#pragma unroll
            for (int mt = 0; mt < 2; mt++) {
                int row = wm * 32 + mt * 16 + (mi & 1) * 8 + ri;
                int col = kb + (mi >> 1) * 8;
                ldsm4(ah[mt], sptr(Ash + row * GS_PAD + col));
                ldsm4(al[mt], sptr(Asl + row * GS_PAD + col));
            }
            int rowb = wn * 16 + (mi >> 1) * 8 + ri;
            int colb = kb + (mi & 1) * 8;
            uint32_t bh[4], bl[4];
            ldsm4(bh, sptr(Bsh + rowb * GS_PAD + colb));
            ldsm4(bl, sptr(Bsl + rowb * GS_PAD + colb));
#pragma unroll
            for (int nt = 0; nt < 2; nt++)
#pragma unroll
                for (int mt = 0; mt < 2; mt++) {
                    mma16(acc[mt][nt], ah[mt], bh[2 * nt], bh[2 * nt + 1]);
                    mma16(acc[mt][nt], al[mt], bh[2 * nt], bh[2 * nt + 1]);
                    mma16(acc[mt][nt], ah[mt], bl[2 * nt], bl[2 * nt + 1]);
                }
        }
    }

    float sp = 0.f;
    if (MODE == 2) sp = log1pf(expf(dts[kidx]));
    const int ocolbase = which * (nblk * 64) + col0;
#pragma unroll
    for (int mt = 0; mt < 2; mt++)
#pragma unroll
        for (int nt = 0; nt < 2; nt++)
#pragma unroll
            for (int e = 0; e < 4; e++) {
                int r = row0 + wm * 32 + mt * 16 + g + ((e >> 1) ? 8 : 0);
                int c = ocolbase + wn * 16 + nt * 8 + 2 * tg + (e & 1);
                float x = acc[mt][nt][e];
                if (MODE == 4) {
                    float y = (which < 2) ? ((x > 0.f) ? (x + 1.f) : expf(x)) : x;
                    __nv_bfloat16 hh, ll; split_bf(y, hh, ll);
                    Oh[(size_t)r * ldo + c] = hh;
                    Ol[(size_t)r * ldo + c] = ll;
                } else {
                    size_t o = (size_t)r * ldc + c;
                    if (MODE == 2)      Cf[o] = aux[o] + sp * x;
                    else if (MODE == 3) Cf[o] = aux[o] + x;
                    else                Cf[o] = x;
                }
            }
}

// ============================================================================
// gemm_bw: wide-tile bf16x3 GEMM (Wup) — R12 known-good
// ============================================================================
#define GW_PAD  72
#define GW_SMEM ((2 * 128 + 2 * 64) * GW_PAD * 2)

__global__ void __launch_bounds__(256)
gemm_bw(const __nv_bfloat16* __restrict__ Agh, const __nv_bfloat16* __restrict__ Agl,
        const __nv_bfloat16* __restrict__ Bgh, const __nv_bfloat16* __restrict__ Bgl,
        int Kd, float* __restrict__ Cf, int ldc)
{
    extern __shared__ __nv_bfloat16 sm[];
    __nv_bfloat16* Ash = sm;
    __nv_bfloat16* Asl = Ash + 128 * GW_PAD;
    __nv_bfloat16* Bsh = Asl + 128 * GW_PAD;
    __nv_bfloat16* Bsl = Bsh + 64 * GW_PAD;

    const int tid  = threadIdx.x;
    const int lane = tid & 31, wid = tid >> 5;
    const int g = lane >> 2, tg = lane & 3;
    const int mi = lane >> 3, ri = lane & 7;
    const int wm = wid & 3, wn = wid >> 2;
    const int col0 = blockIdx.x * 64;
    const int row0 = blockIdx.y * 128;

    float acc[2][4][4];
#pragma unroll
    for (int a = 0; a < 2; a++)
#pragma unroll
        for (int b = 0; b < 4; b++)
#pragma unroll
            for (int c = 0; c < 4; c++) acc[a][b][c] = 0.f;

    for (int kt = 0; kt < Kd; kt += 64) {
        __syncthreads();
#pragma unroll
        for (int it = 0; it < 8; it++) {
            int f  = it * 256 + tid;
            int pl = f >> 10;
            int r  = (f >> 3) & 127;
            int c8 = (f & 7) * 8;
            __nv_bfloat16* dst = (pl ? Asl : Ash) + r * GW_PAD + c8;
            const __nv_bfloat16* src = (pl ? Agl : Agh) + (size_t)(row0 + r) * Kd + kt + c8;
            *(uint4*)dst = *(const uint4*)src;
        }
#pragma unroll
        for (int it = 0; it < 4; it++) {
            int f  = it * 256 + tid;
            int pl = f >> 9;
            int r  = (f >> 3) & 63;
            int c8 = (f & 7) * 8;
            __nv_bfloat16* dst = (pl ? Bsl : Bsh) + r * GW_PAD + c8;
            const __nv_bfloat16* src = (pl ? Bgl : Bgh) + (size_t)(col0 + r) * Kd + kt + c8;
            *(uint4*)dst = *(const uint4*)src;
        }
        __syncthreads();

#pragma unroll
        for (int ks = 0; ks < 4; ks++) {
            int kb = ks * 16;
            uint32_t ah[2][4], al[2][4];
#pragma unroll
            for (int mt = 0; mt < 2; mt++) {
                int row = wm * 32 + mt * 16 + (mi & 1) * 8 + ri;
                int col = kb + (mi >> 1) * 8;
                ldsm4(ah[mt], sptr(Ash + row * GW_PAD + col));
                ldsm4(al[mt], sptr(Asl + row * GW_PAD + col));
            }
            uint32_t bh[2][4], bl[2][4];
#pragma unroll
            for (int np = 0; np < 2; np++) {
                int rowb = wn * 32 + np * 16 + (mi >> 1) * 8 + ri;
                int colb = kb + (mi & 1) * 8;
                ldsm4(bh[np], sptr(Bsh + rowb * GW_PAD + colb));
                ldsm4(bl[np], sptr(Bsl + rowb * GW_PAD + colb));
            }
#pragma unroll
            for (int np = 0; np < 2; np++)
#pragma unroll
                for (int sub = 0; sub < 2; sub++) {
                    int nt = np * 2 + sub;
#pragma unroll
                    for (int mt = 0; mt < 2; mt++) {
                        mma16(acc[mt][nt], ah[mt], bh[np][2 * sub], bh[np][2 * sub + 1]);
                        mma16(acc[mt][nt], al[mt], bh[np][2 * sub], bh[np][2 * sub + 1]);
                        mma16(acc[mt][nt], ah[mt], bl[np][2 * sub], bl[np][2 * sub + 1]);
                    }
                }
        }
    }

#pragma unroll
    for (int mt = 0; mt < 2; mt++)
#pragma unroll
        for (int nt = 0; nt < 4; nt++)
#pragma unroll
            for (int e = 0; e < 4; e++) {
                int r = row0 + wm * 32 + mt * 16 + g + ((e >> 1) ? 8 : 0);
                int c = col0 + wn * 32 + nt * 8 + 2 * tg + (e & 1);
                Cf[(size_t)r * ldc + c] = acc[mt][nt][e];
            }
}

// ============================================================================
// gemm_lm: tf32 x1 LM head (fp32 in, fp32 out), 128x64x32 tiles — R6 known-good
// ============================================================================
#define GL_SMEM (((128 * 33) + (32 * 65)) * 4)

__global__ void __launch_bounds__(256, 2)
gemm_lm(const float* __restrict__ A, const float* __restrict__ Bm, float* __restrict__ C,
        int N, int Kd)
{
    extern __shared__ uint32_t shl[];
    uint32_t* Ah = shl;                      // 128*33
    uint32_t* Bh = Ah + 128 * 33;            // 32*65

    const int tid  = threadIdx.x;
    const int lane = tid & 31;
    const int wid  = tid >> 5;
    const int g  = lane >> 2, tg = lane & 3;
    const int wm = wid & 3,   wn = wid >> 2;
    const int row0 = blockIdx.y * 128;
    const int col0 = blockIdx.x * 64;

    float acc[2][4][4];
#pragma unroll
    for (int a = 0; a < 2; a++)
#pragma unroll
        for (int b = 0; b < 4; b++)
#pragma unroll
            for (int c = 0; c < 4; c++) acc[a][b][c] = 0.f;

    for (int kt = 0; kt < Kd; kt += 32) {
        __syncthreads();
#pragma unroll
        for (int it = 0; it < 4; it++) {
            int flat = it * 256 + tid;
            int m  = flat >> 3;
            int kq = (flat & 7) << 2;
            float4 av = *(const float4*)(A + (size_t)(row0 + m) * Kd + kt + kq);
            Ah[m * 33 + kq + 0] = cvt_tf32(av.x);
            Ah[m * 33 + kq + 1] = cvt_tf32(av.y);
            Ah[m * 33 + kq + 2] = cvt_tf32(av.z);
            Ah[m * 33 + kq + 3] = cvt_tf32(av.w);
        }
#pragma unroll
        for (int it = 0; it < 2; it++) {
            int flat = it * 256 + tid;
            int kk = flat >> 4;
            int nq = (flat & 15) << 2;
            float4 bv = *(const float4*)(Bm + (size_t)(kt + kk) * N + col0 + nq);
            Bh[kk * 65 + nq + 0] = cvt_tf32(bv.x);
            Bh[kk * 65 + nq + 1] = cvt_tf32(bv.y);
            Bh[kk * 65 + nq + 2] = cvt_tf32(bv.z);
            Bh[kk * 65 + nq + 3] = cvt_tf32(bv.w);
        }
        __syncthreads();

#pragma unroll
        for (int ks = 0; ks < 4; ks++) {
            int kb = ks * 8;
            uint32_t ah[2][4];
#pragma unroll
            for (int mt = 0; mt < 2; mt++) {
                int r = wm * 32 + mt * 16;
                ah[mt][0] = Ah[(r + g) * 33 + kb + tg];
                ah[mt][1] = Ah[(r + g + 8) * 33 + kb + tg];
                ah[mt][2] = Ah[(r + g) * 33 + kb + tg + 4];
                ah[mt][3] = Ah[(r + g + 8) * 33 + kb + tg + 4];
            }
#pragma unroll
            for (int nt = 0; nt < 4; nt++) {
                int c = wn * 32 + nt * 8;
                uint32_t bh0 = Bh[(kb + tg) * 65 + c + g];
                uint32_t bh1 = Bh[(kb + tg + 4) * 65 + c + g];
#pragma unroll
                for (int mt = 0; mt < 2; mt++) mma8(acc[mt][nt], ah[mt], bh0, bh1);
            }
        }
    }

#pragma unroll
    for (int mt = 0; mt < 2; mt++)
#pragma unroll
        for (int nt = 0; nt < 4; nt++)
#pragma unroll
            for (int e = 0; e < 4; e++) {
                int r = row0 + wm * 32 + mt * 16 + g + ((e >> 1) ? 8 : 0);
                int c = col0 + wn * 32 + nt * 8 + 2 * tg + (e & 1);
                C[(size_t)r * N + c] = acc[mt][nt][e];
            }
}

// ============================================================================
// attn_bs (R12 known-good)
// ============================================================================
#define AT_PAD   40
#define AT_PLANE (64 * AT_PAD)
#define AT_SMEM  ((2 + 8) * AT_PLANE * 2 + (4 * 32 * 16 + 4 * 32 * 2) * 4)

__global__ void __launch_bounds__(256)
attn_bs(const __nv_bfloat16* __restrict__ qkvh, const __nv_bfloat16* __restrict__ qkvl,
        __nv_bfloat16* __restrict__ cmvh, __nv_bfloat16* __restrict__ cmvl)
{
    extern __shared__ __nv_bfloat16 smb[];
    __nv_bfloat16* qh = smb;
    __nv_bfloat16* ql = qh + AT_PLANE;
    __nv_bfloat16* kv = ql + AT_PLANE;
    float* cred = (float*)(kv + 8 * AT_PLANE);
    float* sred = cred + 4 * 32 * 16;

    const int tid  = threadIdx.x;
    const int lane = tid & 31, wid = tid >> 5;
    const int w4 = wid & 3, wg = wid >> 2;
    const int g = lane >> 2, tg = lane & 3;
    const int mi = lane >> 3, ri = lane & 7;
    const int b = blockIdx.x >> 3, h = blockIdx.x & 7;
    const int qb = blockIdx.y;
    const size_t qrow0 = (size_t)(b * N_ + qb * 64);

    const int kr  = tid >> 2;
    const int kj8 = (tid & 3) * 8;

    uint4 prkv[8];
#pragma unroll
    for (int p = 0; p < 8; p++) {
        int sub = p & 3;
        const __nv_bfloat16* srcp = (sub & 1) ? qkvl : qkvh;
        int colofs = ((sub < 2) ? D_ : 2 * D_) + h * DH_ + kj8;
        size_t row = (size_t)(b * N_ + (p >> 2) * 64 + kr);
        prkv[p] = *(const uint4*)(srcp + row * (3 * D_) + colofs);
    }

#pragma unroll
    for (int it = 0; it < 2; it++) {
        int f  = it * 256 + tid;
        int pl = f >> 8;
        int r  = (f >> 2) & 63;
        int j  = f & 3;
        const __nv_bfloat16* src = (pl ? qkvl : qkvh) + (qrow0 + r) * (3 * D_) + h * DH_ + j * 8;
        *(uint4*)((pl ? ql : qh) + r * AT_PAD + j * 8) = *(const uint4*)src;
    }
    __syncthreads();

    uint32_t qfh[2][4], qfl[2][4];
    {
        int row = w4 * 16 + (mi & 1) * 8 + ri;
#pragma unroll
        for (int ks = 0; ks < 2; ks++) {
            int col = ks * 16 + (mi >> 1) * 8;
            ldsm4(qfh[ks], sptr(qh + row * AT_PAD + col));
            ldsm4(qfl[ks], sptr(ql + row * AT_PAD + col));
        }
    }

    float cacc[4][4];
#pragma unroll
    for (int nt = 0; nt < 4; nt++)
#pragma unroll
        for (int e = 0; e < 4; e++) cacc[nt][e] = 0.f;
    float sr0 = 0.f, sr1 = 0.f;

    __nv_bfloat16* mykv = kv + wg * 4 * AT_PLANE;

    for (int t = 0; t < 8; t++) {
        __syncthreads();
#pragma unroll
        for (int p = 0; p < 8; p++)
            *(uint4*)(kv + p * AT_PLANE + kr * AT_PAD + kj8) = prkv[p];
        __syncthreads();
        if (t + 1 < 8) {
#pragma unroll
            for (int p = 0; p < 8; p++) {
                int sub = p & 3;
                const __nv_bfloat16* srcp = (sub & 1) ? qkvl : qkvh;
                int colofs = ((sub < 2) ? D_ : 2 * D_) + h * DH_ + kj8;
                size_t row = (size_t)(b * N_ + (2 * (t + 1) + (p >> 2)) * 64 + kr);
                prkv[p] = *(const uint4*)(srcp + row * (3 * D_) + colofs);
            }
        }

        const __nv_bfloat16* khp = mykv;
        const __nv_bfloat16* klp = mykv + AT_PLANE;
        const __nv_bfloat16* vhp = mykv + 2 * AT_PLANE;
        const __nv_bfloat16* vlp = mykv + 3 * AT_PLANE;

        float sacc[8][4];
#pragma unroll
        for (int nt = 0; nt < 8; nt++)
#pragma unroll
            for (int e = 0; e < 4; e++) sacc[nt][e] = 0.f;

#pragma unroll
        for (int ks = 0; ks < 2; ks++) {
            int kb = ks * 16;
#pragma unroll
            for (int np = 0; np < 4; np++) {
                int rown = np * 16 + (mi >> 1) * 8 + ri;
                int coln = kb + (mi & 1) * 8;
                uint32_t bh[4], bl[4];
                ldsm4(bh, sptr(khp + rown * AT_PAD + coln));
                ldsm4(bl, sptr(klp + rown * AT_PAD + coln));
                mma16(sacc[np * 2 + 0], qfh[ks], bh[0], bh[1]);
                mma16(sacc[np * 2 + 0], qfl[ks], bh[0], bh[1]);
                mma16(sacc[np * 2 + 0], qfh[ks], bl[0], bl[1]);
                mma16(sacc[np * 2 + 1], qfh[ks], bh[2], bh[3]);
                mma16(sacc[np * 2 + 1], qfl[ks], bh[2], bh[3]);
                mma16(sacc[np * 2 + 1], qfh[ks], bl[2], bl[3]);
            }
        }
#pragma unroll
        for (int nt = 0; nt < 8; nt++) {
#pragma unroll
            for (int e = 0; e < 4; e++) {
                float w = fmaxf(sacc[nt][e], 0.f);
                sacc[nt][e] = w * w;
            }
            sr0 += sacc[nt][0] + sacc[nt][1];
            sr1 += sacc[nt][2] + sacc[nt][3];
        }

#pragma unroll
        for (int ks2 = 0; ks2 < 4; ks2++) {
            uint32_t ph[4], pl4[4];
            {
                float r0 = sacc[2 * ks2][0],     r1 = sacc[2 * ks2][1];
                float r2 = sacc[2 * ks2][2],     r3 = sacc[2 * ks2][3];
                float r4 = sacc[2 * ks2 + 1][0], r5 = sacc[2 * ks2 + 1][1];
                float r6 = sacc[2 * ks2 + 1][2], r7 = sacc[2 * ks2 + 1][3];
                __nv_bfloat16 h0, l0, h1, l1;
                split_bf(r0, h0, l0); split_bf(r1, h1, l1);
                ph[0] = pack2f(__bfloat162float(h0), __bfloat162float(h1));
                pl4[0] = pack2f(__bfloat162float(l0), __bfloat162float(l1));
                split_bf(r2, h0, l0); split_bf(r3, h1, l1);
                ph[1] = pack2f(__bfloat162float(h0), __bfloat162float(h1));
                pl4[1] = pack2f(__bfloat162float(l0), __bfloat162float(l1));
                split_bf(r4, h0, l0); split_bf(r5, h1, l1);
                ph[2] = pack2f(__bfloat162float(h0), __bfloat162float(h1));
                pl4[2] = pack2f(__bfloat162float(l0), __bfloat162float(l1));
                split_bf(r6, h0, l0); split_bf(r7, h1, l1);
                ph[3] = pack2f(__bfloat162float(h0), __bfloat162float(h1));
                pl4[3] = pack2f(__bfloat162float(l0), __bfloat162float(l1));
            }
            int rowv = ks2 * 16 + (mi & 1) * 8 + ri;
#pragma unroll
            for (int dp = 0; dp < 2; dp++) {
                int colv = (dp * 2 + (mi >> 1)) * 8;
                uint32_t bh[4], bl[4];
                ldsm4t(bh, sptr(vhp + rowv * AT_PAD + colv));
                ldsm4t(bl, sptr(vlp + rowv * AT_PAD + colv));
                mma16(cacc[dp * 2 + 0], ph, bh[0], bh[1]);
                mma16(cacc[dp * 2 + 0], pl4, bh[0], bh[1]);
                mma16(cacc[dp * 2 + 0], ph, bl[0], bl[1]);
                mma16(cacc[dp * 2 + 1], ph, bh[2], bh[3]);
                mma16(cacc[dp * 2 + 1], pl4, bh[2], bh[3]);
                mma16(cacc[dp * 2 + 1], ph, bl[2], bl[3]);
            }
        }
    }

    __syncthreads();
    if (wg == 1) {
        float* cd = cred + (w4 * 32 + lane) * 16;
#pragma unroll
        for (int nt = 0; nt < 4; nt++)
#pragma unroll
            for (int e = 0; e < 4; e++) cd[nt * 4 + e] = cacc[nt][e];
        sred[(w4 * 32 + lane) * 2 + 0] = sr0;
        sred[(w4 * 32 + lane) * 2 + 1] = sr1;
    }
    __syncthreads();
    if (wg == 0) {
        const float* cd = cred + (w4 * 32 + lane) * 16;
#pragma unroll
        for (int nt = 0; nt < 4; nt++)
#pragma unroll
            for (int e = 0; e < 4; e++) cacc[nt][e] += cd[nt * 4 + e];
        sr0 += sred[(w4 * 32 + lane) * 2 + 0];
        sr1 += sred[(w4 * 32 + lane) * 2 + 1];
        sr0 += __shfl_xor_sync(0xffffffffu, sr0, 1);
        sr0 += __shfl_xor_sync(0xffffffffu, sr0, 2);
        sr1 += __shfl_xor_sync(0xffffffffu, sr1, 1);
        sr1 += __shfl_xor_sync(0xffffffffu, sr1, 2);
        float inv0 = 1.f / (sr0 + 1.f);
        float inv1 = 1.f / (sr1 + 1.f);

#pragma unroll
        for (int nt = 0; nt < 4; nt++)
#pragma unroll
            for (int e = 0; e < 4; e++) {
                int rl = w4 * 16 + g + ((e >> 1) ? 8 : 0);
                int dh = nt * 8 + 2 * tg + (e & 1);
                size_t row = qrow0 + rl;
                size_t vof = row * (3 * D_) + 2 * D_ + h * DH_ + dh;
                float vv = __bfloat162float(qkvh[vof]) + __bfloat162float(qkvl[vof]);
                float y = cacc[nt][e] * ((e >> 1) ? inv1 : inv0) - vv;
                __nv_bfloat16 hh, ll; split_bf(y, hh, ll);
                cmvh[row * D_ + h * DH_ + dh] = hh;
                cmvl[row * D_ + h * DH_ + dh] = ll;
            }
    }
}

// ---------------- silu-conv / halt ----------------
__global__ void siluconv_split(const float* __restrict__ gu, const float* __restrict__ cw,
                               int kidx, __nv_bfloat16* __restrict__ oh,
                               __nv_bfloat16* __restrict__ ol) {
    int idx = blockIdx.x * 256 + threadIdx.x;
    int i   = idx & (IN_ - 1);
    int bn  = idx >> 10;
    int n   = bn & (N_ - 1);
    const float* wp = cw + ((size_t)kidx * IN_ + i) * CK_;
    float gC = gu[(size_t)bn * (2 * IN_) + i];
    float uC = gu[(size_t)bn * (2 * IN_) + IN_ + i];
    float a = wp[1] * (gC / (1.f + expf(-gC)) * uC);
    if (n > 0) {
        float gm = gu[(size_t)(bn - 1) * (2 * IN_) + i];
        float um = gu[(size_t)(bn - 1) * (2 * IN_) + IN_ + i];
        a = fmaf(wp[0], gm / (1.f + expf(-gm)) * um, a);
    }
    if (n < N_ - 1) {
        float gp = gu[(size_t)(bn + 1) * (2 * IN_) + i];
        float up = gu[(size_t)(bn + 1) * (2 * IN_) + IN_ + i];
        a = fmaf(wp[2], gp / (1.f + expf(-gp)) * up, a);
    }
    __nv_bfloat16 hh, ll; split_bf(a, hh, ll);
    oh[idx] = hh;
    ol[idx] = ll;
}

__global__ void __launch_bounds__(256)
halt_dot(const float* __restrict__ qn, const float* __restrict__ hw, float* __restrict__ hd) {
    int row  = blockIdx.x * 8 + (threadIdx.x >> 5);
    int lane = threadIdx.x & 31;
    const float* ip = qn + (size_t)row * D_;
    float s = 0.f;
#pragma unroll
    for (int j = 0; j < 8; j++) s = fmaf(ip[j * 32 + lane], hw[j * 32 + lane], s);
    s = warpReduceSum(s);
    if (lane == 0) hd[row] = s;
}

__global__ void __launch_bounds__(1024)
halt_fin(const float* __restrict__ hd, const float* __restrict__ hb,
         float* __restrict__ out, int l4) {
    __shared__ float sh[32];
    int b = blockIdx.x;
    float v = hd[(size_t)b * N_ + threadIdx.x];
    v = warpReduceSum(v);
    if ((threadIdx.x & 31) == 0) sh[threadIdx.x >> 5] = v;
    __syncthreads();
    if (threadIdx.x < 32) {
        float t = sh[threadIdx.x];
        t = warpReduceSum(t);
        if (threadIdx.x == 0)
            out[l4 * B_ + b] = 1.f / (1.f + expf(-(t * (1.f / N_) + hb[0])));
    }
}

// ---------------- host orchestration ----------------
static inline void* symp(const void* sym) {
    void* p = nullptr;
    cudaGetSymbolAddress(&p, sym);
    return p;
}

extern "C" void kernel_launch(void* const* d_in, const int* in_sizes, int n_in,
                              void* d_out, int out_size) {
    const int*   ids   = (const int*)  d_in[0];
    const float* emb   = (const float*)d_in[1];
    const float* pos   = (const float*)d_in[2];
    const float* in_w  = (const float*)d_in[3];
    const float* in_b  = (const float*)d_in[4];
    const float* Wq    = (const float*)d_in[5];
    const float* Wk    = (const float*)d_in[6];
    const float* Wv    = (const float*)d_in[7];
    const float* Wo    = (const float*)d_in[8];
    const float* dts   = (const float*)d_in[9];
    const float* Wup   = (const float*)d_in[10];
    const float* cw    = (const float*)d_in[11];
    const float* Wd    = (const float*)d_in[12];
    const float* n1w   = (const float*)d_in[13];
    const float* n1b   = (const float*)d_in[14];
    const float* n2w   = (const float*)d_in[15];
    const float* n2b   = (const float*)d_in[16];
    const float* fin_w = (const float*)d_in[17];
    const float* fin_b = (const float*)d_in[18];
    const float* haltw = (const float*)d_in[19];
    const float* haltb = (const float*)d_in[20];
    const float* lm_w  = (const float*)d_in[21];

    float* out        = (float*)d_out;
    float* out_logits = out;
    float* out_halts  = out + (size_t)out_size - (size_t)(MAXL_ - TRUNC_) * B_;

    float* pX  = (float*)symp(g_X);
    float* pQ  = (float*)symp(g_Q);
    float* pGU = (float*)symp(g_gu);
    float* pQn0 = (float*)symp(g_qn);
    float* pHd0 = (float*)symp(g_hd);

    __nv_bfloat16* pHcH = (__nv_bfloat16*)symp(g_hc_h),  *pHcL = (__nv_bfloat16*)symp(g_hc_l);
    __nv_bfloat16* pQkH = (__nv_bfloat16*)symp(g_qkv_h), *pQkL = (__nv_bfloat16*)symp(g_qkv_l);
    __nv_bfloat16* pCmH = (__nv_bfloat16*)symp(g_cmv_h), *pCmL = (__nv_bfloat16*)symp(g_cmv_l);
    __nv_bfloat16* pHnH = (__nv_bfloat16*)symp(g_hn_h),  *pHnL = (__nv_bfloat16*)symp(g_hn_l);
    __nv_bfloat16* pH2H = (__nv_bfloat16*)symp(g_hc2_h), *pH2L = (__nv_bfloat16*)symp(g_hc2_l);
    __nv_bfloat16* pQnH0 = (__nv_bfloat16*)symp(g_qn_h), *pQnL0 = (__nv_bfloat16*)symp(g_qn_l);

    __nv_bfloat16* pWqH = (__nv_bfloat16*)symp(g_wq_h),  *pWqL = (__nv_bfloat16*)symp(g_wq_l);
    __nv_bfloat16* pWkH = (__nv_bfloat16*)symp(g_wk_h),  *pWkL = (__nv_bfloat16*)symp(g_wk_l);
    __nv_bfloat16* pWvH = (__nv_bfloat16*)symp(g_wv_h),  *pWvL = (__nv_bfloat16*)symp(g_wv_l);
    __nv_bfloat16* pWoH = (__nv_bfloat16*)symp(g_wo_h),  *pWoL = (__nv_bfloat16*)symp(g_wo_l);
    __nv_bfloat16* pWuH = (__nv_bfloat16*)symp(g_wup_h), *pWuL = (__nv_bfloat16*)symp(g_wup_l);
    __nv_bfloat16* pWdH = (__nv_bfloat16*)symp(g_wd_h),  *pWdL = (__nv_bfloat16*)symp(g_wd_l);

    cudaFuncSetAttribute(gemm_bs<2>, cudaFuncAttributeMaxDynamicSharedMemorySize, GS_SMEM);
    cudaFuncSetAttribute(gemm_bs<3>, cudaFuncAttributeMaxDynamicSharedMemorySize, GS_SMEM);
    cudaFuncSetAttribute(gemm_bs<4>, cudaFuncAttributeMaxDynamicSharedMemorySize, GS_SMEM);
    cudaFuncSetAttribute(gemm_bw,    cudaFuncAttributeMaxDynamicSharedMemorySize, GW_SMEM);
    cudaFuncSetAttribute(gemm_lm,    cudaFuncAttributeMaxDynamicSharedMemorySize, GL_SMEM);
    cudaFuncSetAttribute(attn_bs,    cudaFuncAttributeMaxDynamicSharedMemorySize, AT_SMEM);

    const dim3 tb(32, 8);
    tsplit<<<dim3(8, 8, 4),  tb>>>(Wq,  pWqH, pWqL, D_,  D_);
    tsplit<<<dim3(8, 8, 4),  tb>>>(Wk,  pWkH, pWkL, D_,  D_);
    tsplit<<<dim3(8, 8, 4),  tb>>>(Wv,  pWvH, pWvL, D_,  D_);
    tsplit<<<dim3(8, 8, 4),  tb>>>(Wo,  pWoH, pWoL, D_,  D_);
    tsplit<<<dim3(64, 8, 4), tb>>>(Wup, pWuH, pWuL, D_,  2 * IN_);
    tsplit<<<dim3(8, 32, 4), tb>>>(Wd,  pWdH, pWdL, IN_, D_);

    embed_kernel<<<BN_, 256>>>(ids, emb, pos, pX);
    ln_kernel<<<BN_, 256>>>(pX, in_w, in_b, pX, pQ);

    const dim3 gQKV(12, BN_ / 64);
    const dim3 gDD(4, BN_ / 64);
    const dim3 gUP(2 * IN_ / 64, BN_ / 128);
    const dim3 gLM(V_ / 64, BN_ / 128);
    const dim3 gAT(B_ * H_, N_ / 64);
    const int  ec = (BN_ * IN_) / 256;
    const int  lnb = BN_ / 8;
    bool side_used = false;

    for (int l = 0; l < MAXL_; l++) {
        for (int k = 0; k < K_; k++) {
            size_t wo = (size_t)k * D_ * D_;
            ln_split<<<lnb, 256>>>(pQ, n1w + k * D_, n1b + k * D_, pX, pHcH, pHcL, nullptr);
            gemm_bs<4><<<gQKV, 256, GS_SMEM>>>(pHcH, pHcL,
                                               pWqH + wo, pWqL + wo,
                                               pWkH + wo, pWkL + wo,
                                               pWvH + wo, pWvL + wo,
                                               D_, 4, nullptr, 0,
                                               pQkH, pQkL, 3 * D_, nullptr, nullptr, 0);
            attn_bs<<<gAT, 256, AT_SMEM>>>(pQkH, pQkL, pCmH, pCmL);
            gemm_bs<2><<<gDD, 256, GS_SMEM>>>(pCmH, pCmL,
                                              pWoH + wo, pWoL + wo,
                                              pWoH + wo, pWoL + wo,
                                              pWoH + wo, pWoL + wo,
                                              D_, 4, pQ, D_,
                                              nullptr, nullptr, 0, pQ, dts, k);
            ln_split<<<lnb, 256>>>(pQ, n2w + k * D_, n2b + k * D_, nullptr, pHnH, pHnL, nullptr);
            size_t wu = (size_t)k * D_ * 2 * IN_;
            gemm_bw<<<gUP, 256, GW_SMEM>>>(pHnH, pHnL, pWuH + wu, pWuL + wu,
                                           D_, pGU, 2 * IN_);
            siluconv_split<<<ec, 256>>>(pGU, cw, k, pH2H, pH2L);
            size_t wd = (size_t)k * IN_ * D_;
            gemm_bs<3><<<gDD, 256, GS_SMEM>>>(pH2H, pH2L,
                                              pWdH + wd, pWdL + wd,
                                              pWdH + wd, pWdL + wd,
                                              pWdH + wd, pWdL + wd,
                                              IN_, 4, pQ, D_,
                                              nullptr, nullptr, 0, pQ, nullptr, 0);
        }
        if (l >= TRUNC_) {
            int l4 = l - TRUNC_;
            int pb = l4 & 1;
            float*         pQn  = pQn0  + (size_t)pb * BN_ * D_;
            float*         pHd  = pHd0  + (size_t)pb * BN_;
            __nv_bfloat16* pQnH = pQnH0 + (size_t)pb * BN_ * D_;
            __nv_bfloat16* pQnL = pQnL0 + (size_t)pb * BN_ * D_;

            ln_split<<<lnb, 256>>>(pQ, fin_w, fin_b, nullptr, pQnH, pQnL, pQn);

            cudaEventRecord(g_sc.f, 0);
            cudaStreamWaitEvent(g_sc.s, g_sc.f, 0);
            halt_dot<<<lnb, 256, 0, g_sc.s>>>(pQn, haltw, pHd);
            halt_fin<<<B_, 1024, 0, g_sc.s>>>(pHd, haltb, out_halts, l4);
            gemm_lm<<<gLM, 256, GL_SMEM, g_sc.s>>>(pQn, lm_w,
                                                   out_logits + (size_t)l4 * BN_ * V_,
                                                   V_, D_);
            side_used = true;
        }
    }

    if (side_used) {
        cudaEventRecord(g_sc.j, g_sc.s);
        cudaStreamWaitEvent(0, g_sc.j, 0);
    }
}

// round 15
// speedup vs baseline: 1.5187x; 1.5187x over previous
#include <cuda_runtime.h>
#include <cuda_fp16.h>
#include <math.h>
#include <stdint.h>

#define B_    2
#define N_    1024
#define D_    256
#define H_    8
#define DH_   32
#define K_    4
#define IN_   1024
#define V_    32000
#define CK_   3
#define MAXL_ 8
#define TRUNC_ 4
#define BN_   (B_ * N_)

// ---------------- fp32 scratch ----------------
__device__ float g_X [BN_ * D_];
__device__ float g_Q [BN_ * D_];
__device__ float g_gu[BN_ * 2 * IN_];
__device__ float g_qn[2][BN_ * D_];
__device__ float g_hd[2][BN_];

// ---------------- activation split planes (fp16 hi/lo) ----------------
__device__ __align__(16) __half g_hc_h [BN_ * D_],     g_hc_l [BN_ * D_];
__device__ __align__(16) __half g_qkv_h[BN_ * 3 * D_], g_qkv_l[BN_ * 3 * D_];
__device__ __align__(16) __half g_cmv_h[BN_ * D_],     g_cmv_l[BN_ * D_];
__device__ __align__(16) __half g_hn_h [BN_ * D_],     g_hn_l [BN_ * D_];
__device__ __align__(16) __half g_hc2_h[BN_ * IN_],    g_hc2_l[BN_ * IN_];
__device__ __align__(16) __half g_qn_h [2][BN_ * D_],  g_qn_l [2][BN_ * D_];

// ---------------- transposed weights [n][k], fp16 hi only (B side) ----
__device__ __align__(16) __half g_wq_h [K_ * D_ * D_];
__device__ __align__(16) __half g_wk_h [K_ * D_ * D_];
__device__ __align__(16) __half g_wv_h [K_ * D_ * D_];
__device__ __align__(16) __half g_wo_h [K_ * D_ * D_];
__device__ __align__(16) __half g_wup_h[K_ * 2 * IN_ * D_];
__device__ __align__(16) __half g_wd_h [K_ * D_ * IN_];
__device__ __align__(16) __half g_lm_h [(size_t)V_ * D_];

// ---------------- side stream + events ----------------
struct SideCtx {
    cudaStream_t s;
    cudaEvent_t  f, j;
    SideCtx() {
        cudaStreamCreateWithFlags(&s, cudaStreamNonBlocking);
        cudaEventCreateWithFlags(&f, cudaEventDisableTiming);
        cudaEventCreateWithFlags(&j, cudaEventDisableTiming);
    }
};
static SideCtx g_sc;

// ---------------- helpers ----------------
__device__ __forceinline__ void split_hf(float v, __half& h, __half& l) {
    h = __float2half_rn(v);
    l = __float2half_rn(v - __half2float(h));
}
__device__ __forceinline__ uint32_t pack2h(__half a, __half b) {
    __half2 t = __halves2half2(a, b);
    return *reinterpret_cast<uint32_t*>(&t);
}
__device__ __forceinline__ uint32_t sptr(const void* p) {
    return (uint32_t)__cvta_generic_to_shared(p);
}
__device__ __forceinline__ void ldsm4(uint32_t* r, uint32_t sa) {
    asm volatile("ldmatrix.sync.aligned.m8n8.x4.shared.b16 {%0,%1,%2,%3}, [%4];"
                 : "=r"(r[0]), "=r"(r[1]), "=r"(r[2]), "=r"(r[3]) : "r"(sa));
}
__device__ __forceinline__ void ldsm4t(uint32_t* r, uint32_t sa) {
    asm volatile("ldmatrix.sync.aligned.m8n8.x4.trans.shared.b16 {%0,%1,%2,%3}, [%4];"
                 : "=r"(r[0]), "=r"(r[1]), "=r"(r[2]), "=r"(r[3]) : "r"(sa));
}
__device__ __forceinline__ void mma16(float* c, const uint32_t* a, uint32_t b0, uint32_t b1) {
    asm volatile("mma.sync.aligned.m16n8k16.row.col.f32.f16.f16.f32 "
                 "{%0,%1,%2,%3}, {%4,%5,%6,%7}, {%8,%9}, {%0,%1,%2,%3};"
                 : "+f"(c[0]), "+f"(c[1]), "+f"(c[2]), "+f"(c[3])
                 : "r"(a[0]), "r"(a[1]), "r"(a[2]), "r"(a[3]), "r"(b0), "r"(b1));
}
__device__ __forceinline__ float warpReduceSum(float v) {
#pragma unroll
    for (int o = 16; o > 0; o >>= 1) v += __shfl_xor_sync(0xffffffffu, v, o);
    return v;
}
__device__ __forceinline__ float blockReduceSum256(float v) {
    __shared__ float sh[8];
    int lane = threadIdx.x & 31;
    int wid  = threadIdx.x >> 5;
#pragma unroll
    for (int o = 16; o > 0; o >>= 1) v += __shfl_down_sync(0xffffffffu, v, o);
    __syncthreads();
    if (lane == 0) sh[wid] = v;
    __syncthreads();
    float t = 0.f;
#pragma unroll
    for (int i = 0; i < 8; i++) t += sh[i];
    return t;
}

// ---------------- weight transpose + fp16 quantize (hi only) ----------------
__global__ void wsplit(const float* __restrict__ W, __half* __restrict__ oh,
                       int Kd, int Nn)
{
    __shared__ float t[32][33];
    const float* Wz = W + (size_t)blockIdx.z * Kd * Nn;
    __half* ohz = oh + (size_t)blockIdx.z * Kd * Nn;
    int n0 = blockIdx.x * 32, k0 = blockIdx.y * 32;
    int tx = threadIdx.x, ty = threadIdx.y;
#pragma unroll
    for (int i = 0; i < 4; i++)
        t[ty + i * 8][tx] = Wz[(size_t)(k0 + ty + i * 8) * Nn + n0 + tx];
    __syncthreads();
#pragma unroll
    for (int i = 0; i < 4; i++) {
        int n = ty + i * 8;
        ohz[(size_t)(n0 + n) * Kd + k0 + tx] = __float2half_rn(t[tx][n]);
    }
}

// ---------------- embedding / LN ----------------
__global__ void embed_kernel(const int* __restrict__ ids, const float* __restrict__ emb,
                             const float* __restrict__ pos, float* __restrict__ X) {
    int row = blockIdx.x, d = threadIdx.x;
    int n = row & (N_ - 1);
    X[(size_t)row * D_ + d] = emb[(size_t)ids[row] * D_ + d] + pos[(size_t)n * D_ + d];
}

__global__ void ln_kernel(const float* __restrict__ in, const float* __restrict__ w,
                          const float* __restrict__ b, float* __restrict__ out,
                          float* __restrict__ out2) {
    int row = blockIdx.x, d = threadIdx.x;
    float x  = in[(size_t)row * D_ + d];
    float mu = blockReduceSum256(x) * (1.f / D_);
    float dx = x - mu;
    float var = blockReduceSum256(dx * dx) * (1.f / D_);
    float y = dx * rsqrtf(var + 1e-5f) * w[d] + b[d];
    out[(size_t)row * D_ + d] = y;
    if (out2) out2[(size_t)row * D_ + d] = y;
}

__global__ void __launch_bounds__(256)
ln_split(const float* __restrict__ in, const float* __restrict__ w,
         const float* __restrict__ b, const float* __restrict__ addX,
         __half* __restrict__ oh, __half* __restrict__ ol,
         float* __restrict__ ofp) {
    int row  = blockIdx.x * 8 + (threadIdx.x >> 5);
    int lane = threadIdx.x & 31;
    const float* ip = in + (size_t)row * D_;
    float x[8], s = 0.f;
#pragma unroll
    for (int j = 0; j < 8; j++) { x[j] = ip[j * 32 + lane]; s += x[j]; }
    float mu = warpReduceSum(s) * (1.f / D_);
    float v = 0.f;
#pragma unroll
    for (int j = 0; j < 8; j++) { float dx = x[j] - mu; v += dx * dx; }
    float rs = rsqrtf(warpReduceSum(v) * (1.f / D_) + 1e-5f);
#pragma unroll
    for (int j = 0; j < 8; j++) {
        int d = j * 32 + lane;
        float y = (x[j] - mu) * rs * w[d] + b[d];
        if (addX) y += addX[(size_t)row * D_ + d];
        __half hh, ll; split_hf(y, hh, ll);
        oh[(size_t)row * D_ + d] = hh;
        ol[(size_t)row * D_ + d] = ll;
        if (ofp) ofp[(size_t)row * D_ + d] = y;
    }
}

// ============================================================================
// gemm_bs: fp16x2 GEMM (A hi/lo planes, B hi plane), 64x64x64 tiles,
//   8 warps (2m x 4n), ldmatrix, register double-buffer.
// MODE: 0 fp32 store; 2 aux + softplus(dts[kidx])*x; 3 aux + x;
//       4 split-plane store (elu+1 when which<2)   [QKV]
// ============================================================================
#define GS_PAD  72
#define GS_SMEM (3 * 64 * GS_PAD * 2)

template <int MODE>
__global__ void __launch_bounds__(256)
gemm_bs(const __half* __restrict__ Agh, const __half* __restrict__ Agl,
        const __half* __restrict__ B0h, const __half* __restrict__ B1h,
        const __half* __restrict__ B2h,
        int Kd, int nblk,
        float* __restrict__ Cf, int ldc,
        __half* __restrict__ Oh, __half* __restrict__ Ol, int ldo,
        const float* __restrict__ aux, const float* __restrict__ dts, int kidx)
{
    extern __shared__ __half sm[];
    __half* Ash = sm;
    __half* Asl = Ash + 64 * GS_PAD;
    __half* Bsh = Asl + 64 * GS_PAD;

    const int tid  = threadIdx.x;
    const int lane = tid & 31, wid = tid >> 5;
    const int g = lane >> 2, tg = lane & 3;
    const int mi = lane >> 3, ri = lane & 7;
    const int wm = wid & 1, wn = wid >> 1;
    const int which = blockIdx.x / nblk;
    const int bxl   = blockIdx.x - which * nblk;
    const int col0  = bxl * 64;
    const int row0  = blockIdx.y * 64;
    const __half* Bgh = (which == 0) ? B0h : (which == 1) ? B1h : B2h;

    const int r0 = tid >> 3;
    const int c0 = (tid & 7) * 8;
    const __half* sA0 = Agh + (size_t)(row0 + r0) * Kd + c0;
    const __half* sA1 = Agl + (size_t)(row0 + r0) * Kd + c0;
    const __half* sB0 = Bgh + (size_t)(col0 + r0) * Kd + c0;
    const size_t rstep = (size_t)32 * Kd;

    float acc[2][2][4];
#pragma unroll
    for (int a = 0; a < 2; a++)
#pragma unroll
        for (int b = 0; b < 2; b++)
#pragma unroll
            for (int c = 0; c < 4; c++) acc[a][b][c] = 0.f;

    const int niter = Kd >> 6;
    uint4 pr[6];
    pr[0] = *(const uint4*)(sA0);
    pr[1] = *(const uint4*)(sA0 + rstep);
    pr[2] = *(const uint4*)(sA1);
    pr[3] = *(const uint4*)(sA1 + rstep);
    pr[4] = *(const uint4*)(sB0);
    pr[5] = *(const uint4*)(sB0 + rstep);

    for (int it2 = 0; it2 < niter; it2++) {
        __syncthreads();
        *(uint4*)(Ash + r0 * GS_PAD + c0)        = pr[0];
        *(uint4*)(Ash + (r0 + 32) * GS_PAD + c0) = pr[1];
        *(uint4*)(Asl + r0 * GS_PAD + c0)        = pr[2];
        *(uint4*)(Asl + (r0 + 32) * GS_PAD + c0) = pr[3];
        *(uint4*)(Bsh + r0 * GS_PAD + c0)        = pr[4];
        *(uint4*)(Bsh + (r0 + 32) * GS_PAD + c0) = pr[5];
        __syncthreads();
        if (it2 + 1 < niter) {
            int o = (it2 + 1) * 64;
            pr[0] = *(const uint4*)(sA0 + o);
            pr[1] = *(const uint4*)(sA0 + rstep + o);
            pr[2] = *(const uint4*)(sA1 + o);
            pr[3] = *(const uint4*)(sA1 + rstep + o);
            pr[4] = *(const uint4*)(sB0 + o);
            pr[5] = *(const uint4*)(sB0 + rstep + o);
        }

#pragma unroll
        for (int ks = 0; ks < 4; ks++) {
            int kb = ks * 16;
            uint32_t ah[2][4], al[2][4];
#pragma unroll
            for (int mt = 0; mt < 2; mt++) {
                int row = wm * 32 + mt * 16 + (mi & 1) * 8 + ri;
                int col = kb + (mi >> 1) * 8;
                ldsm4(ah[mt], sptr(Ash + row * GS_PAD + col));
                ldsm4(al[mt], sptr(Asl + row * GS_PAD + col));
            }
            int rowb = wn * 16 + (mi >> 1) * 8 + ri;
            int colb = kb + (mi & 1) * 8;
            uint32_t bh[4];
            ldsm4(bh, sptr(Bsh + rowb * GS_PAD + colb));
#pragma unroll
            for (int nt = 0; nt < 2; nt++)
#pragma unroll
                for (int mt = 0; mt < 2; mt++) {
                    mma16(acc[mt][nt], ah[mt], bh[2 * nt], bh[2 * nt + 1]);
                    mma16(acc[mt][nt], al[mt], bh[2 * nt], bh[2 * nt + 1]);
                }
        }
    }

    float sp = 0.f;
    if (MODE == 2) sp = log1pf(expf(dts[kidx]));
    const int ocolbase = which * (nblk * 64) + col0;
#pragma unroll
    for (int mt = 0; mt < 2; mt++)
#pragma unroll
        for (int nt = 0; nt < 2; nt++)
#pragma unroll
            for (int e = 0; e < 4; e++) {
                int r = row0 + wm * 32 + mt * 16 + g + ((e >> 1) ? 8 : 0);
                int c = ocolbase + wn * 16 + nt * 8 + 2 * tg + (e & 1);
                float x = acc[mt][nt][e];
                if (MODE == 4) {
                    float y = (which < 2) ? ((x > 0.f) ? (x + 1.f) : expf(x)) : x;
                    __half hh, ll; split_hf(y, hh, ll);
                    Oh[(size_t)r * ldo + c] = hh;
                    Ol[(size_t)r * ldo + c] = ll;
                } else {
                    size_t o = (size_t)r * ldc + c;
                    if (MODE == 2)      Cf[o] = aux[o] + sp * x;
                    else if (MODE == 3) Cf[o] = aux[o] + x;
                    else                Cf[o] = x;
                }
            }
}

// ============================================================================
// gemm_bw: fp16x2 wide-tile GEMM (Wup / LM head), 128x64 tiles, fp32 out.
// ============================================================================
#define GW_PAD  72
#define GW_SMEM ((2 * 128 + 64) * GW_PAD * 2)

__global__ void __launch_bounds__(256)
gemm_bw(const __half* __restrict__ Agh, const __half* __restrict__ Agl,
        const __half* __restrict__ Bgh,
        int Kd, float* __restrict__ Cf, int ldc)
{
    extern __shared__ __half sm[];
    __half* Ash = sm;
    __half* Asl = Ash + 128 * GW_PAD;
    __half* Bsh = Asl + 128 * GW_PAD;

    const int tid  = threadIdx.x;
    const int lane = tid & 31, wid = tid >> 5;
    const int g = lane >> 2, tg = lane & 3;
    const int mi = lane >> 3, ri = lane & 7;
    const int wm = wid & 3, wn = wid >> 2;
    const int col0 = blockIdx.x * 64;
    const int row0 = blockIdx.y * 128;

    float acc[2][4][4];
#pragma unroll
    for (int a = 0; a < 2; a++)
#pragma unroll
        for (int b = 0; b < 4; b++)
#pragma unroll
            for (int c = 0; c < 4; c++) acc[a][b][c] = 0.f;

    for (int kt = 0; kt < Kd; kt += 64) {
        __syncthreads();
#pragma unroll
        for (int it = 0; it < 8; it++) {
            int f  = it * 256 + tid;            // A planes: 2048 uint4
            int pl = f >> 10;
            int r  = (f >> 3) & 127;
            int c8 = (f & 7) * 8;
            __half* dst = (pl ? Asl : Ash) + r * GW_PAD + c8;
            const __half* src = (pl ? Agl : Agh) + (size_t)(row0 + r) * Kd + kt + c8;
            *(uint4*)dst = *(const uint4*)src;
        }
#pragma unroll
        for (int it = 0; it < 2; it++) {
            int f  = it * 256 + tid;            // B hi plane: 512 uint4
            int r  = f >> 3;
            int c8 = (f & 7) * 8;
            *(uint4*)(Bsh + r * GW_PAD + c8) =
                *(const uint4*)(Bgh + (size_t)(col0 + r) * Kd + kt + c8);
        }
        __syncthreads();

#pragma unroll
        for (int ks = 0; ks < 4; ks++) {
            int kb = ks * 16;
            uint32_t ah[2][4], al[2][4];
#pragma unroll
            for (int mt = 0; mt < 2; mt++) {
                int row = wm * 32 + mt * 16 + (mi & 1) * 8 + ri;
                int col = kb + (mi >> 1) * 8;
                ldsm4(ah[mt], sptr(Ash + row * GW_PAD + col));
                ldsm4(al[mt], sptr(Asl + row * GW_PAD + col));
            }
            uint32_t bh[2][4];
#pragma unroll
            for (int np = 0; np < 2; np++) {
                int rowb = wn * 32 + np * 16 + (mi >> 1) * 8 + ri;
                int colb = kb + (mi & 1) * 8;
                ldsm4(bh[np], sptr(Bsh + rowb * GW_PAD + colb));
            }
#pragma unroll
            for (int np = 0; np < 2; np++)
#pragma unroll
                for (int sub = 0; sub < 2; sub++) {
                    int nt = np * 2 + sub;
#pragma unroll
                    for (int mt = 0; mt < 2; mt++) {
                        mma16(acc[mt][nt], ah[mt], bh[np][2 * sub], bh[np][2 * sub + 1]);
                        mma16(acc[mt][nt], al[mt], bh[np][2 * sub], bh[np][2 * sub + 1]);
                    }
                }
        }
    }

#pragma unroll
    for (int mt = 0; mt < 2; mt++)
#pragma unroll
        for (int nt = 0; nt < 4; nt++)
#pragma unroll
            for (int e = 0; e < 4; e++) {
                int r = row0 + wm * 32 + mt * 16 + g + ((e >> 1) ? 8 : 0);
                int c = col0 + wn * 32 + nt * 8 + 2 * tg + (e & 1);
                Cf[(size_t)r * ldc + c] = acc[mt][nt][e];
            }
}

// ============================================================================
// attn_bs: flash-style fp16x2. q hi/lo (A), k hi (B), v hi (B).
// ============================================================================
#define AT_PAD   40
#define AT_PLANE (64 * AT_PAD)
#define AT_SMEM  ((2 + 4) * AT_PLANE * 2 + (4 * 32 * 16 + 4 * 32 * 2) * 4)

__global__ void __launch_bounds__(256)
attn_bs(const __half* __restrict__ qkvh, const __half* __restrict__ qkvl,
        __half* __restrict__ cmvh, __half* __restrict__ cmvl)
{
    extern __shared__ __half smb[];
    __half* qh = smb;
    __half* ql = qh + AT_PLANE;
    __half* kv = ql + AT_PLANE;                 // 4 planes: [t0:kh,vh][t1:kh,vh]
    float* cred = (float*)(kv + 4 * AT_PLANE);  // [128][16]
    float* sred = cred + 4 * 32 * 16;           // [128][2]

    const int tid  = threadIdx.x;
    const int lane = tid & 31, wid = tid >> 5;
    const int w4 = wid & 3, wg = wid >> 2;
    const int g = lane >> 2, tg = lane & 3;
    const int mi = lane >> 3, ri = lane & 7;
    const int b = blockIdx.x >> 3, h = blockIdx.x & 7;
    const int qb = blockIdx.y;
    const size_t qrow0 = (size_t)(b * N_ + qb * 64);

    // kv staging: 4 planes x 64 rows x 4 chunks = 1024 uint4 / 256 thr = 4 each
    const int kr  = tid >> 2;
    const int kj8 = (tid & 3) * 8;

    uint4 prkv[4];
#pragma unroll
    for (int p = 0; p < 4; p++) {
        int isv = p & 1;
        int colofs = (isv ? 2 * D_ : D_) + h * DH_ + kj8;
        size_t row = (size_t)(b * N_ + (p >> 1) * 64 + kr);
        prkv[p] = *(const uint4*)(qkvh + row * (3 * D_) + colofs);
    }

#pragma unroll
    for (int it = 0; it < 2; it++) {
        int f  = it * 256 + tid;
        int pl = f >> 8;
        int r  = (f >> 2) & 63;
        int j  = f & 3;
        const __half* src = (pl ? qkvl : qkvh) + (qrow0 + r) * (3 * D_) + h * DH_ + j * 8;
        *(uint4*)((pl ? ql : qh) + r * AT_PAD + j * 8) = *(const uint4*)src;
    }
    __syncthreads();

    uint32_t qfh[2][4], qfl[2][4];
    {
        int row = w4 * 16 + (mi & 1) * 8 + ri;
#pragma unroll
        for (int ks = 0; ks < 2; ks++) {
            int col = ks * 16 + (mi >> 1) * 8;
            ldsm4(qfh[ks], sptr(qh + row * AT_PAD + col));
            ldsm4(qfl[ks], sptr(ql + row * AT_PAD + col));
        }
    }

    float cacc[4][4];
#pragma unroll
    for (int nt = 0; nt < 4; nt++)
#pragma unroll
        for (int e = 0; e < 4; e++) cacc[nt][e] = 0.f;
    float sr0 = 0.f, sr1 = 0.f;

    __half* mykv = kv + wg * 2 * AT_PLANE;

    for (int t = 0; t < 8; t++) {
        __syncthreads();
#pragma unroll
        for (int p = 0; p < 4; p++)
            *(uint4*)(kv + p * AT_PLANE + kr * AT_PAD + kj8) = prkv[p];
        __syncthreads();
        if (t + 1 < 8) {
#pragma unroll
            for (int p = 0; p < 4; p++) {
                int isv = p & 1;
                int colofs = (isv ? 2 * D_ : D_) + h * DH_ + kj8;
                size_t row = (size_t)(b * N_ + (2 * (t + 1) + (p >> 1)) * 64 + kr);
                prkv[p] = *(const uint4*)(qkvh + row * (3 * D_) + colofs);
            }
        }

        const __half* khp = mykv;
        const __half* vhp = mykv + AT_PLANE;

        // ---- phase 1: S = pq @ pk^T ----
        float sacc[8][4];
#pragma unroll
        for (int nt = 0; nt < 8; nt++)
#pragma unroll
            for (int e = 0; e < 4; e++) sacc[nt][e] = 0.f;

#pragma unroll
        for (int ks = 0; ks < 2; ks++) {
            int kb = ks * 16;
#pragma unroll
            for (int np = 0; np < 4; np++) {
                int rown = np * 16 + (mi >> 1) * 8 + ri;
                int coln = kb + (mi & 1) * 8;
                uint32_t bh[4];
                ldsm4(bh, sptr(khp + rown * AT_PAD + coln));
                mma16(sacc[np * 2 + 0], qfh[ks], bh[0], bh[1]);
                mma16(sacc[np * 2 + 0], qfl[ks], bh[0], bh[1]);
                mma16(sacc[np * 2 + 1], qfh[ks], bh[2], bh[3]);
                mma16(sacc[np * 2 + 1], qfl[ks], bh[2], bh[3]);
            }
        }
        // relu^2 + rowsum partials
#pragma unroll
        for (int nt = 0; nt < 8; nt++) {
#pragma unroll
            for (int e = 0; e < 4; e++) {
                float w = fmaxf(sacc[nt][e], 0.f);
                sacc[nt][e] = w * w;
            }
            sr0 += sacc[nt][0] + sacc[nt][1];
            sr1 += sacc[nt][2] + sacc[nt][3];
        }

        // ---- phase 2: C += P @ v ----
#pragma unroll
        for (int ks2 = 0; ks2 < 4; ks2++) {
            uint32_t ph[4], pl4[4];
            {
                __half h0, l0, h1, l1;
                split_hf(sacc[2 * ks2][0], h0, l0); split_hf(sacc[2 * ks2][1], h1, l1);
                ph[0] = pack2h(h0, h1); pl4[0] = pack2h(l0, l1);
                split_hf(sacc[2 * ks2][2], h0, l0); split_hf(sacc[2 * ks2][3], h1, l1);
                ph[1] = pack2h(h0, h1); pl4[1] = pack2h(l0, l1);
                split_hf(sacc[2 * ks2 + 1][0], h0, l0); split_hf(sacc[2 * ks2 + 1][1], h1, l1);
                ph[2] = pack2h(h0, h1); pl4[2] = pack2h(l0, l1);
                split_hf(sacc[2 * ks2 + 1][2], h0, l0); split_hf(sacc[2 * ks2 + 1][3], h1, l1);
                ph[3] = pack2h(h0, h1); pl4[3] = pack2h(l0, l1);
            }
            int rowv = ks2 * 16 + (mi & 1) * 8 + ri;
#pragma unroll
            for (int dp = 0; dp < 2; dp++) {
                int colv = (dp * 2 + (mi >> 1)) * 8;
                uint32_t bh[4];
                ldsm4t(bh, sptr(vhp + rowv * AT_PAD + colv));
                mma16(cacc[dp * 2 + 0], ph, bh[0], bh[1]);
                mma16(cacc[dp * 2 + 0], pl4, bh[0], bh[1]);
                mma16(cacc[dp * 2 + 1], ph, bh[2], bh[3]);
                mma16(cacc[dp * 2 + 1], pl4, bh[2], bh[3]);
            }
        }
    }

    __syncthreads();
    if (wg == 1) {
        float* cd = cred + (w4 * 32 + lane) * 16;
#pragma unroll
        for (int nt = 0; nt < 4; nt++)
#pragma unroll
            for (int e = 0; e < 4; e++) cd[nt * 4 + e] = cacc[nt][e];
        sred[(w4 * 32 + lane) * 2 + 0] = sr0;
        sred[(w4 * 32 + lane) * 2 + 1] = sr1;
    }
    __syncthreads();
    if (wg == 0) {
        const float* cd = cred + (w4 * 32 + lane) * 16;
#pragma unroll
        for (int nt = 0; nt < 4; nt++)
#pragma unroll
            for (int e = 0; e < 4; e++) cacc[nt][e] += cd[nt * 4 + e];
        sr0 += sred[(w4 * 32 + lane) * 2 + 0];
        sr1 += sred[(w4 * 32 + lane) * 2 + 1];
        sr0 += __shfl_xor_sync(0xffffffffu, sr0, 1);
        sr0 += __shfl_xor_sync(0xffffffffu, sr0, 2);
        sr1 += __shfl_xor_sync(0xffffffffu, sr1, 1);
        sr1 += __shfl_xor_sync(0xffffffffu, sr1, 2);
        float inv0 = 1.f / (sr0 + 1.f);
        float inv1 = 1.f / (sr1 + 1.f);

#pragma unroll
        for (int nt = 0; nt < 4; nt++)
#pragma unroll
            for (int e = 0; e < 4; e++) {
                int rl = w4 * 16 + g + ((e >> 1) ? 8 : 0);
                int dh = nt * 8 + 2 * tg + (e & 1);
                size_t row = qrow0 + rl;
                size_t vof = row * (3 * D_) + 2 * D_ + h * DH_ + dh;
                float vv = __half2float(qkvh[vof]) + __half2float(qkvl[vof]);
                float y = cacc[nt][e] * ((e >> 1) ? inv1 : inv0) - vv;
                __half hh, ll; split_hf(y, hh, ll);
                cmvh[row * D_ + h * DH_ + dh] = hh;
                cmvl[row * D_ + h * DH_ + dh] = ll;
            }
    }
}

// ---------------- silu-conv / halt ----------------
__global__ void siluconv_split(const float* __restrict__ gu, const float* __restrict__ cw,
                               int kidx, __half* __restrict__ oh,
                               __half* __restrict__ ol) {
    int idx = blockIdx.x * 256 + threadIdx.x;
    int i   = idx & (IN_ - 1);
    int bn  = idx >> 10;
    int n   = bn & (N_ - 1);
    const float* wp = cw + ((size_t)kidx * IN_ + i) * CK_;
    float gC = gu[(size_t)bn * (2 * IN_) + i];
    float uC = gu[(size_t)bn * (2 * IN_) + IN_ + i];
    float a = wp[1] * (gC / (1.f + expf(-gC)) * uC);
    if (n > 0) {
        float gm = gu[(size_t)(bn - 1) * (2 * IN_) + i];
        float um = gu[(size_t)(bn - 1) * (2 * IN_) + IN_ + i];
        a = fmaf(wp[0], gm / (1.f + expf(-gm)) * um, a);
    }
    if (n < N_ - 1) {
        float gp = gu[(size_t)(bn + 1) * (2 * IN_) + i];
        float up = gu[(size_t)(bn + 1) * (2 * IN_) + IN_ + i];
        a = fmaf(wp[2], gp / (1.f + expf(-gp)) * up, a);
    }
    __half hh, ll; split_hf(a, hh, ll);
    oh[idx] = hh;
    ol[idx] = ll;
}

__global__ void __launch_bounds__(256)
halt_dot(const float* __restrict__ qn, const float* __restrict__ hw, float* __restrict__ hd) {
    int row  = blockIdx.x * 8 + (threadIdx.x >> 5);
    int lane = threadIdx.x & 31;
    const float* ip = qn + (size_t)row * D_;
    float s = 0.f;
#pragma unroll
    for (int j = 0; j < 8; j++) s = fmaf(ip[j * 32 + lane], hw[j * 32 + lane], s);
    s = warpReduceSum(s);
    if (lane == 0) hd[row] = s;
}

__global__ void __launch_bounds__(1024)
halt_fin(const float* __restrict__ hd, const float* __restrict__ hb,
         float* __restrict__ out, int l4) {
    __shared__ float sh[32];
    int b = blockIdx.x;
    float v = hd[(size_t)b * N_ + threadIdx.x];
    v = warpReduceSum(v);
    if ((threadIdx.x & 31) == 0) sh[threadIdx.x >> 5] = v;
    __syncthreads();
    if (threadIdx.x < 32) {
        float t = sh[threadIdx.x];
        t = warpReduceSum(t);
        if (threadIdx.x == 0)
            out[l4 * B_ + b] = 1.f / (1.f + expf(-(t * (1.f / N_) + hb[0])));
    }
}

// ---------------- host orchestration ----------------
static inline void* symp(const void* sym) {
    void* p = nullptr;
    cudaGetSymbolAddress(&p, sym);
    return p;
}

extern "C" void kernel_launch(void* const* d_in, const int* in_sizes, int n_in,
                              void* d_out, int out_size) {
    const int*   ids   = (const int*)  d_in[0];
    const float* emb   = (const float*)d_in[1];
    const float* pos   = (const float*)d_in[2];
    const float* in_w  = (const float*)d_in[3];
    const float* in_b  = (const float*)d_in[4];
    const float* Wq    = (const float*)d_in[5];
    const float* Wk    = (const float*)d_in[6];
    const float* Wv    = (const float*)d_in[7];
    const float* Wo    = (const float*)d_in[8];
    const float* dts   = (const float*)d_in[9];
    const float* Wup   = (const float*)d_in[10];
    const float* cw    = (const float*)d_in[11];
    const float* Wd    = (const float*)d_in[12];
    const float* n1w   = (const float*)d_in[13];
    const float* n1b   = (const float*)d_in[14];
    const float* n2w   = (const float*)d_in[15];
    const float* n2b   = (const float*)d_in[16];
    const float* fin_w = (const float*)d_in[17];
    const float* fin_b = (const float*)d_in[18];
    const float* haltw = (const float*)d_in[19];
    const float* haltb = (const float*)d_in[20];
    const float* lm_w  = (const float*)d_in[21];

    float* out        = (float*)d_out;
    float* out_logits = out;
    float* out_halts  = out + (size_t)out_size - (size_t)(MAXL_ - TRUNC_) * B_;

    float* pX  = (float*)symp(g_X);
    float* pQ  = (float*)symp(g_Q);
    float* pGU = (float*)symp(g_gu);
    float* pQn0 = (float*)symp(g_qn);
    float* pHd0 = (float*)symp(g_hd);

    __half* pHcH = (__half*)symp(g_hc_h),  *pHcL = (__half*)symp(g_hc_l);
    __half* pQkH = (__half*)symp(g_qkv_h), *pQkL = (__half*)symp(g_qkv_l);
    __half* pCmH = (__half*)symp(g_cmv_h), *pCmL = (__half*)symp(g_cmv_l);
    __half* pHnH = (__half*)symp(g_hn_h),  *pHnL = (__half*)symp(g_hn_l);
    __half* pH2H = (__half*)symp(g_hc2_h), *pH2L = (__half*)symp(g_hc2_l);
    __half* pQnH0 = (__half*)symp(g_qn_h), *pQnL0 = (__half*)symp(g_qn_l);

    __half* pWqH = (__half*)symp(g_wq_h);
    __half* pWkH = (__half*)symp(g_wk_h);
    __half* pWvH = (__half*)symp(g_wv_h);
    __half* pWoH = (__half*)symp(g_wo_h);
    __half* pWuH = (__half*)symp(g_wup_h);
    __half* pWdH = (__half*)symp(g_wd_h);
    __half* pLmH = (__half*)symp(g_lm_h);

    cudaFuncSetAttribute(gemm_bs<2>, cudaFuncAttributeMaxDynamicSharedMemorySize, GS_SMEM);
    cudaFuncSetAttribute(gemm_bs<3>, cudaFuncAttributeMaxDynamicSharedMemorySize, GS_SMEM);
    cudaFuncSetAttribute(gemm_bs<4>, cudaFuncAttributeMaxDynamicSharedMemorySize, GS_SMEM);
    cudaFuncSetAttribute(gemm_bw,    cudaFuncAttributeMaxDynamicSharedMemorySize, GW_SMEM);
    cudaFuncSetAttribute(attn_bs,    cudaFuncAttributeMaxDynamicSharedMemorySize, AT_SMEM);

    const dim3 tb(32, 8);
    wsplit<<<dim3(8, 8, 4),    tb>>>(Wq,   pWqH, D_,  D_);
    wsplit<<<dim3(8, 8, 4),    tb>>>(Wk,   pWkH, D_,  D_);
    wsplit<<<dim3(8, 8, 4),    tb>>>(Wv,   pWvH, D_,  D_);
    wsplit<<<dim3(8, 8, 4),    tb>>>(Wo,   pWoH, D_,  D_);
    wsplit<<<dim3(64, 8, 4),   tb>>>(Wup,  pWuH, D_,  2 * IN_);
    wsplit<<<dim3(8, 32, 4),   tb>>>(Wd,   pWdH, IN_, D_);
    wsplit<<<dim3(1000, 8, 1), tb>>>(lm_w, pLmH, D_,  V_);

    embed_kernel<<<BN_, 256>>>(ids, emb, pos, pX);
    ln_kernel<<<BN_, 256>>>(pX, in_w, in_b, pX, pQ);

    const dim3 gQKV(12, BN_ / 64);
    const dim3 gDD(4, BN_ / 64);
    const dim3 gUP(2 * IN_ / 64, BN_ / 128);
    const dim3 gLM(V_ / 64, BN_ / 128);
    const dim3 gAT(B_ * H_, N_ / 64);
    const int  ec = (BN_ * IN_) / 256;
    const int  lnb = BN_ / 8;
    bool side_used = false;

    for (int l = 0; l < MAXL_; l++) {
        for (int k = 0; k < K_; k++) {
            size_t wo = (size_t)k * D_ * D_;
            ln_split<<<lnb, 256>>>(pQ, n1w + k * D_, n1b + k * D_, pX, pHcH, pHcL, nullptr);
            gemm_bs<4><<<gQKV, 256, GS_SMEM>>>(pHcH, pHcL,
                                               pWqH + wo, pWkH + wo, pWvH + wo,
                                               D_, 4, nullptr, 0,
                                               pQkH, pQkL, 3 * D_, nullptr, nullptr, 0);
            attn_bs<<<gAT, 256, AT_SMEM>>>(pQkH, pQkL, pCmH, pCmL);
            gemm_bs<2><<<gDD, 256, GS_SMEM>>>(pCmH, pCmL,
                                              pWoH + wo, pWoH + wo, pWoH + wo,
                                              D_, 4, pQ, D_,
                                              nullptr, nullptr, 0, pQ, dts, k);
            ln_split<<<lnb, 256>>>(pQ, n2w + k * D_, n2b + k * D_, nullptr, pHnH, pHnL, nullptr);
            size_t wu = (size_t)k * D_ * 2 * IN_;
            gemm_bw<<<gUP, 256, GW_SMEM>>>(pHnH, pHnL, pWuH + wu, D_, pGU, 2 * IN_);
            siluconv_split<<<ec, 256>>>(pGU, cw, k, pH2H, pH2L);
            size_t wd = (size_t)k * IN_ * D_;
            gemm_bs<3><<<gDD, 256, GS_SMEM>>>(pH2H, pH2L,
                                              pWdH + wd, pWdH + wd, pWdH + wd,
                                              IN_, 4, pQ, D_,
                                              nullptr, nullptr, 0, pQ, nullptr, 0);
        }
        if (l >= TRUNC_) {
            int l4 = l - TRUNC_;
            int pb = l4 & 1;
            float*  pQn  = pQn0  + (size_t)pb * BN_ * D_;
            float*  pHd  = pHd0  + (size_t)pb * BN_;
            __half* pQnH = pQnH0 + (size_t)pb * BN_ * D_;
            __half* pQnL = pQnL0 + (size_t)pb * BN_ * D_;

            ln_split<<<lnb, 256>>>(pQ, fin_w, fin_b, nullptr, pQnH, pQnL, pQn);

            cudaEventRecord(g_sc.f, 0);
            cudaStreamWaitEvent(g_sc.s, g_sc.f, 0);
            halt_dot<<<lnb, 256, 0, g_sc.s>>>(pQn, haltw, pHd);
            halt_fin<<<B_, 1024, 0, g_sc.s>>>(pHd, haltb, out_halts, l4);
            gemm_bw<<<gLM, 256, GW_SMEM, g_sc.s>>>(pQnH, pQnL, pLmH,
                                                   D_, out_logits + (size_t)l4 * BN_ * V_, V_);
            side_used = true;
        }
    }

    if (side_used) {
        cudaEventRecord(g_sc.j, g_sc.s);
        cudaStreamWaitEvent(0, g_sc.j, 0);
    }
}

// round 16
// speedup vs baseline: 1.6919x; 1.1141x over previous
#include <cuda_runtime.h>
#include <cuda_fp16.h>
#include <math.h>
#include <stdint.h>

#define B_    2
#define N_    1024
#define D_    256
#define H_    8
#define DH_   32
#define K_    4
#define IN_   1024
#define V_    32000
#define CK_   3
#define MAXL_ 8
#define TRUNC_ 4
#define BN_   (B_ * N_)

// ---------------- fp32 scratch ----------------
__device__ float g_X [BN_ * D_];
__device__ float g_Q [BN_ * D_];
__device__ float g_gu[BN_ * 2 * IN_];
__device__ float g_qn[2][BN_ * D_];
__device__ float g_hd[2][BN_];

// ---------------- activation split planes (fp16 hi/lo) ----------------
__device__ __align__(16) __half g_hc_h [BN_ * D_],     g_hc_l [BN_ * D_];
__device__ __align__(16) __half g_qkv_h[BN_ * 3 * D_], g_qkv_l[BN_ * 3 * D_];
__device__ __align__(16) __half g_cmv_h[BN_ * D_],     g_cmv_l[BN_ * D_];
__device__ __align__(16) __half g_hn_h [BN_ * D_],     g_hn_l [BN_ * D_];
__device__ __align__(16) __half g_hc2_h[BN_ * IN_],    g_hc2_l[BN_ * IN_];
__device__ __align__(16) __half g_qn_h [2][BN_ * D_];

// ---------------- transposed weights [n][k], fp16 hi only (B side) ----
__device__ __align__(16) __half g_wq_h [K_ * D_ * D_];
__device__ __align__(16) __half g_wk_h [K_ * D_ * D_];
__device__ __align__(16) __half g_wv_h [K_ * D_ * D_];
__device__ __align__(16) __half g_wo_h [K_ * D_ * D_];
__device__ __align__(16) __half g_wup_h[K_ * 2 * IN_ * D_];
__device__ __align__(16) __half g_wd_h [K_ * D_ * IN_];
__device__ __align__(16) __half g_lm_h [(size_t)V_ * D_];

// ---------------- side stream + events ----------------
struct SideCtx {
    cudaStream_t s;
    cudaEvent_t  f, j;
    SideCtx() {
        cudaStreamCreateWithFlags(&s, cudaStreamNonBlocking);
        cudaEventCreateWithFlags(&f, cudaEventDisableTiming);
        cudaEventCreateWithFlags(&j, cudaEventDisableTiming);
    }
};
static SideCtx g_sc;

// ---------------- helpers ----------------
__device__ __forceinline__ void split_hf(float v, __half& h, __half& l) {
    h = __float2half_rn(v);
    l = __float2half_rn(v - __half2float(h));
}
__device__ __forceinline__ uint32_t pack2h(__half a, __half b) {
    __half2 t = __halves2half2(a, b);
    return *reinterpret_cast<uint32_t*>(&t);
}
__device__ __forceinline__ uint32_t sptr(const void* p) {
    return (uint32_t)__cvta_generic_to_shared(p);
}
__device__ __forceinline__ void ldsm4(uint32_t* r, uint32_t sa) {
    asm volatile("ldmatrix.sync.aligned.m8n8.x4.shared.b16 {%0,%1,%2,%3}, [%4];"
                 : "=r"(r[0]), "=r"(r[1]), "=r"(r[2]), "=r"(r[3]) : "r"(sa));
}
__device__ __forceinline__ void ldsm4t(uint32_t* r, uint32_t sa) {
    asm volatile("ldmatrix.sync.aligned.m8n8.x4.trans.shared.b16 {%0,%1,%2,%3}, [%4];"
                 : "=r"(r[0]), "=r"(r[1]), "=r"(r[2]), "=r"(r[3]) : "r"(sa));
}
__device__ __forceinline__ void mma16(float* c, const uint32_t* a, uint32_t b0, uint32_t b1) {
    asm volatile("mma.sync.aligned.m16n8k16.row.col.f32.f16.f16.f32 "
                 "{%0,%1,%2,%3}, {%4,%5,%6,%7}, {%8,%9}, {%0,%1,%2,%3};"
                 : "+f"(c[0]), "+f"(c[1]), "+f"(c[2]), "+f"(c[3])
                 : "r"(a[0]), "r"(a[1]), "r"(a[2]), "r"(a[3]), "r"(b0), "r"(b1));
}
__device__ __forceinline__ float warpReduceSum(float v) {
#pragma unroll
    for (int o = 16; o > 0; o >>= 1) v += __shfl_xor_sync(0xffffffffu, v, o);
    return v;
}
__device__ __forceinline__ float blockReduceSum256(float v) {
    __shared__ float sh[8];
    int lane = threadIdx.x & 31;
    int wid  = threadIdx.x >> 5;
#pragma unroll
    for (int o = 16; o > 0; o >>= 1) v += __shfl_down_sync(0xffffffffu, v, o);
    __syncthreads();
    if (lane == 0) sh[wid] = v;
    __syncthreads();
    float t = 0.f;
#pragma unroll
    for (int i = 0; i < 8; i++) t += sh[i];
    return t;
}

// ---------------- weight transpose + fp16 quantize (hi only) ----------------
__global__ void wsplit(const float* __restrict__ W, __half* __restrict__ oh,
                       int Kd, int Nn)
{
    __shared__ float t[32][33];
    const float* Wz = W + (size_t)blockIdx.z * Kd * Nn;
    __half* ohz = oh + (size_t)blockIdx.z * Kd * Nn;
    int n0 = blockIdx.x * 32, k0 = blockIdx.y * 32;
    int tx = threadIdx.x, ty = threadIdx.y;
#pragma unroll
    for (int i = 0; i < 4; i++)
        t[ty + i * 8][tx] = Wz[(size_t)(k0 + ty + i * 8) * Nn + n0 + tx];
    __syncthreads();
#pragma unroll
    for (int i = 0; i < 4; i++) {
        int n = ty + i * 8;
        ohz[(size_t)(n0 + n) * Kd + k0 + tx] = __float2half_rn(t[tx][n]);
    }
}

// ---------------- embedding / LN ----------------
__global__ void embed_kernel(const int* __restrict__ ids, const float* __restrict__ emb,
                             const float* __restrict__ pos, float* __restrict__ X) {
    int row = blockIdx.x, d = threadIdx.x;
    int n = row & (N_ - 1);
    X[(size_t)row * D_ + d] = emb[(size_t)ids[row] * D_ + d] + pos[(size_t)n * D_ + d];
}

__global__ void ln_kernel(const float* __restrict__ in, const float* __restrict__ w,
                          const float* __restrict__ b, float* __restrict__ out,
                          float* __restrict__ out2) {
    int row = blockIdx.x, d = threadIdx.x;
    float x  = in[(size_t)row * D_ + d];
    float mu = blockReduceSum256(x) * (1.f / D_);
    float dx = x - mu;
    float var = blockReduceSum256(dx * dx) * (1.f / D_);
    float y = dx * rsqrtf(var + 1e-5f) * w[d] + b[d];
    out[(size_t)row * D_ + d] = y;
    if (out2) out2[(size_t)row * D_ + d] = y;
}

// ln -> split planes (ol optional), warp-per-row
__global__ void __launch_bounds__(256)
ln_split(const float* __restrict__ in, const float* __restrict__ w,
         const float* __restrict__ b, const float* __restrict__ addX,
         __half* __restrict__ oh, __half* __restrict__ ol,
         float* __restrict__ ofp) {
    int row  = blockIdx.x * 8 + (threadIdx.x >> 5);
    int lane = threadIdx.x & 31;
    const float* ip = in + (size_t)row * D_;
    float x[8], s = 0.f;
#pragma unroll
    for (int j = 0; j < 8; j++) { x[j] = ip[j * 32 + lane]; s += x[j]; }
    float mu = warpReduceSum(s) * (1.f / D_);
    float v = 0.f;
#pragma unroll
    for (int j = 0; j < 8; j++) { float dx = x[j] - mu; v += dx * dx; }
    float rs = rsqrtf(warpReduceSum(v) * (1.f / D_) + 1e-5f);
#pragma unroll
    for (int j = 0; j < 8; j++) {
        int d = j * 32 + lane;
        float y = (x[j] - mu) * rs * w[d] + b[d];
        if (addX) y += addX[(size_t)row * D_ + d];
        __half hh, ll; split_hf(y, hh, ll);
        oh[(size_t)row * D_ + d] = hh;
        if (ol) ol[(size_t)row * D_ + d] = ll;
        if (ofp) ofp[(size_t)row * D_ + d] = y;
    }
}

// ============================================================================
// gemm_bs: fp16x2 GEMM (A hi/lo planes, B hi plane), 64x64x64 tiles,
//   8 warps (2m x 4n), ldmatrix, register double-buffer.
// MODE: 0 fp32 store; 2 aux + softplus(dts[kidx])*x; 3 aux + x;
//       4 split-plane store (elu+1 when which<2)   [QKV]
// ============================================================================
#define GS_PAD  72
#define GS_SMEM (3 * 64 * GS_PAD * 2)

template <int MODE>
__global__ void __launch_bounds__(256)
gemm_bs(const __half* __restrict__ Agh, const __half* __restrict__ Agl,
        const __half* __restrict__ B0h, const __half* __restrict__ B1h,
        const __half* __restrict__ B2h,
        int Kd, int nblk,
        float* __restrict__ Cf, int ldc,
        __half* __restrict__ Oh, __half* __restrict__ Ol, int ldo,
        const float* __restrict__ aux, const float* __restrict__ dts, int kidx)
{
    extern __shared__ __half sm[];
    __half* Ash = sm;
    __half* Asl = Ash + 64 * GS_PAD;
    __half* Bsh = Asl + 64 * GS_PAD;

    const int tid  = threadIdx.x;
    const int lane = tid & 31, wid = tid >> 5;
    const int g = lane >> 2, tg = lane & 3;
    const int mi = lane >> 3, ri = lane & 7;
    const int wm = wid & 1, wn = wid >> 1;
    const int which = blockIdx.x / nblk;
    const int bxl   = blockIdx.x - which * nblk;
    const int col0  = bxl * 64;
    const int row0  = blockIdx.y * 64;
    const __half* Bgh = (which == 0) ? B0h : (which == 1) ? B1h : B2h;

    const int r0 = tid >> 3;
    const int c0 = (tid & 7) * 8;
    const __half* sA0 = Agh + (size_t)(row0 + r0) * Kd + c0;
    const __half* sA1 = Agl + (size_t)(row0 + r0) * Kd + c0;
    const __half* sB0 = Bgh + (size_t)(col0 + r0) * Kd + c0;
    const size_t rstep = (size_t)32 * Kd;

    float acc[2][2][4];
#pragma unroll
    for (int a = 0; a < 2; a++)
#pragma unroll
        for (int b = 0; b < 2; b++)
#pragma unroll
            for (int c = 0; c < 4; c++) acc[a][b][c] = 0.f;

    const int niter = Kd >> 6;
    uint4 pr[6];
    pr[0] = *(const uint4*)(sA0);
    pr[1] = *(const uint4*)(sA0 + rstep);
    pr[2] = *(const uint4*)(sA1);
    pr[3] = *(const uint4*)(sA1 + rstep);
    pr[4] = *(const uint4*)(sB0);
    pr[5] = *(const uint4*)(sB0 + rstep);

    for (int it2 = 0; it2 < niter; it2++) {
        __syncthreads();
        *(uint4*)(Ash + r0 * GS_PAD + c0)        = pr[0];
        *(uint4*)(Ash + (r0 + 32) * GS_PAD + c0) = pr[1];
        *(uint4*)(Asl + r0 * GS_PAD + c0)        = pr[2];
        *(uint4*)(Asl + (r0 + 32) * GS_PAD + c0) = pr[3];
        *(uint4*)(Bsh + r0 * GS_PAD + c0)        = pr[4];
        *(uint4*)(Bsh + (r0 + 32) * GS_PAD + c0) = pr[5];
        __syncthreads();
        if (it2 + 1 < niter) {
            int o = (it2 + 1) * 64;
            pr[0] = *(const uint4*)(sA0 + o);
            pr[1] = *(const uint4*)(sA0 + rstep + o);
            pr[2] = *(const uint4*)(sA1 + o);
            pr[3] = *(const uint4*)(sA1 + rstep + o);
            pr[4] = *(const uint4*)(sB0 + o);
            pr[5] = *(const uint4*)(sB0 + rstep + o);
        }

#pragma unroll
        for (int ks = 0; ks < 4; ks++) {
            int kb = ks * 16;
            uint32_t ah[2][4], al[2][4];
#pragma unroll
            for (int mt = 0; mt < 2; mt++) {
                int row = wm * 32 + mt * 16 + (mi & 1) * 8 + ri;
                int col = kb + (mi >> 1) * 8;
                ldsm4(ah[mt], sptr(Ash + row * GS_PAD + col));
                ldsm4(al[mt], sptr(Asl + row * GS_PAD + col));
            }
            int rowb = wn * 16 + (mi >> 1) * 8 + ri;
            int colb = kb + (mi & 1) * 8;
            uint32_t bh[4];
            ldsm4(bh, sptr(Bsh + rowb * GS_PAD + colb));
#pragma unroll
            for (int nt = 0; nt < 2; nt++)
#pragma unroll
                for (int mt = 0; mt < 2; mt++) {
                    mma16(acc[mt][nt], ah[mt], bh[2 * nt], bh[2 * nt + 1]);
                    mma16(acc[mt][nt], al[mt], bh[2 * nt], bh[2 * nt + 1]);
                }
        }
    }

    float sp = 0.f;
    if (MODE == 2) sp = log1pf(expf(dts[kidx]));
    const int ocolbase = which * (nblk * 64) + col0;
#pragma unroll
    for (int mt = 0; mt < 2; mt++)
#pragma unroll
        for (int nt = 0; nt < 2; nt++)
#pragma unroll
            for (int e = 0; e < 4; e++) {
                int r = row0 + wm * 32 + mt * 16 + g + ((e >> 1) ? 8 : 0);
                int c = ocolbase + wn * 16 + nt * 8 + 2 * tg + (e & 1);
                float x = acc[mt][nt][e];
                if (MODE == 4) {
                    float y = (which < 2) ? ((x > 0.f) ? (x + 1.f) : expf(x)) : x;
                    __half hh, ll; split_hf(y, hh, ll);
                    Oh[(size_t)r * ldo + c] = hh;
                    Ol[(size_t)r * ldo + c] = ll;
                } else {
                    size_t o = (size_t)r * ldc + c;
                    if (MODE == 2)      Cf[o] = aux[o] + sp * x;
                    else if (MODE == 3) Cf[o] = aux[o] + x;
                    else                Cf[o] = x;
                }
            }
}

// ============================================================================
// gemm_bw: wide-tile GEMM, 128x64 tiles, fp32 out.
//   ALO=1: A hi+lo (fp16x2, Wup);  ALO=0: A hi only (fp16x1, LM head).
// ============================================================================
#define GW_PAD  72
#define GW_SMEM ((2 * 128 + 64) * GW_PAD * 2)

template <int ALO>
__global__ void __launch_bounds__(256)
gemm_bw(const __half* __restrict__ Agh, const __half* __restrict__ Agl,
        const __half* __restrict__ Bgh,
        int Kd, float* __restrict__ Cf, int ldc)
{
    extern __shared__ __half sm[];
    __half* Ash = sm;
    __half* Asl = Ash + 128 * GW_PAD;
    __half* Bsh = Asl + (ALO ? 128 * GW_PAD : 0);

    const int tid  = threadIdx.x;
    const int lane = tid & 31, wid = tid >> 5;
    const int g = lane >> 2, tg = lane & 3;
    const int mi = lane >> 3, ri = lane & 7;
    const int wm = wid & 3, wn = wid >> 2;
    const int col0 = blockIdx.x * 64;
    const int row0 = blockIdx.y * 128;

    float acc[2][4][4];
#pragma unroll
    for (int a = 0; a < 2; a++)
#pragma unroll
        for (int b = 0; b < 4; b++)
#pragma unroll
            for (int c = 0; c < 4; c++) acc[a][b][c] = 0.f;

    for (int kt = 0; kt < Kd; kt += 64) {
        __syncthreads();
        // A planes: ALO? 2048 : 1024 uint4
#pragma unroll
        for (int it = 0; it < (ALO ? 8 : 4); it++) {
            int f  = it * 256 + tid;
            int pl = ALO ? (f >> 10) : 0;
            int r  = (f >> 3) & 127;
            int c8 = (f & 7) * 8;
            __half* dst = (pl ? Asl : Ash) + r * GW_PAD + c8;
            const __half* src = (pl ? Agl : Agh) + (size_t)(row0 + r) * Kd + kt + c8;
            *(uint4*)dst = *(const uint4*)src;
        }
#pragma unroll
        for (int it = 0; it < 2; it++) {
            int f  = it * 256 + tid;
            int r  = f >> 3;
            int c8 = (f & 7) * 8;
            *(uint4*)(Bsh + r * GW_PAD + c8) =
                *(const uint4*)(Bgh + (size_t)(col0 + r) * Kd + kt + c8);
        }
        __syncthreads();

#pragma unroll
        for (int ks = 0; ks < 4; ks++) {
            int kb = ks * 16;
            uint32_t ah[2][4], al[2][4];
#pragma unroll
            for (int mt = 0; mt < 2; mt++) {
                int row = wm * 32 + mt * 16 + (mi & 1) * 8 + ri;
                int col = kb + (mi >> 1) * 8;
                ldsm4(ah[mt], sptr(Ash + row * GW_PAD + col));
                if (ALO) ldsm4(al[mt], sptr(Asl + row * GW_PAD + col));
            }
            uint32_t bh[2][4];
#pragma unroll
            for (int np = 0; np < 2; np++) {
                int rowb = wn * 32 + np * 16 + (mi >> 1) * 8 + ri;
                int colb = kb + (mi & 1) * 8;
                ldsm4(bh[np], sptr(Bsh + rowb * GW_PAD + colb));
            }
#pragma unroll
            for (int np = 0; np < 2; np++)
#pragma unroll
                for (int sub = 0; sub < 2; sub++) {
                    int nt = np * 2 + sub;
#pragma unroll
                    for (int mt = 0; mt < 2; mt++) {
                        mma16(acc[mt][nt], ah[mt], bh[np][2 * sub], bh[np][2 * sub + 1]);
                        if (ALO) mma16(acc[mt][nt], al[mt], bh[np][2 * sub], bh[np][2 * sub + 1]);
                    }
                }
        }
    }

#pragma unroll
    for (int mt = 0; mt < 2; mt++)
#pragma unroll
        for (int nt = 0; nt < 4; nt++)
#pragma unroll
            for (int e = 0; e < 4; e++) {
                int r = row0 + wm * 32 + mt * 16 + g + ((e >> 1) ? 8 : 0);
                int c = col0 + wn * 32 + nt * 8 + 2 * tg + (e & 1);
                Cf[(size_t)r * ldc + c] = acc[mt][nt][e];
            }
}

// ============================================================================
// attn_bs: flash-style. q hi/lo (A), k hi, v hi, P hi only (phase 2 x1).
// ============================================================================
#define AT_PAD   40
#define AT_PLANE (64 * AT_PAD)
#define AT_SMEM  ((2 + 4) * AT_PLANE * 2 + (4 * 32 * 16 + 4 * 32 * 2) * 4)

__global__ void __launch_bounds__(256)
attn_bs(const __half* __restrict__ qkvh, const __half* __restrict__ qkvl,
        __half* __restrict__ cmvh, __half* __restrict__ cmvl)
{
    extern __shared__ __half smb[];
    __half* qh = smb;
    __half* ql = qh + AT_PLANE;
    __half* kv = ql + AT_PLANE;                 // 4 planes: [t0:kh,vh][t1:kh,vh]
    float* cred = (float*)(kv + 4 * AT_PLANE);  // [128][16]
    float* sred = cred + 4 * 32 * 16;           // [128][2]

    const int tid  = threadIdx.x;
    const int lane = tid & 31, wid = tid >> 5;
    const int w4 = wid & 3, wg = wid >> 2;
    const int g = lane >> 2, tg = lane & 3;
    const int mi = lane >> 3, ri = lane & 7;
    const int b = blockIdx.x >> 3, h = blockIdx.x & 7;
    const int qb = blockIdx.y;
    const size_t qrow0 = (size_t)(b * N_ + qb * 64);

    const int kr  = tid >> 2;
    const int kj8 = (tid & 3) * 8;

    uint4 prkv[4];
#pragma unroll
    for (int p = 0; p < 4; p++) {
        int isv = p & 1;
        int colofs = (isv ? 2 * D_ : D_) + h * DH_ + kj8;
        size_t row = (size_t)(b * N_ + (p >> 1) * 64 + kr);
        prkv[p] = *(const uint4*)(qkvh + row * (3 * D_) + colofs);
    }

#pragma unroll
    for (int it = 0; it < 2; it++) {
        int f  = it * 256 + tid;
        int pl = f >> 8;
        int r  = (f >> 2) & 63;
        int j  = f & 3;
        const __half* src = (pl ? qkvl : qkvh) + (qrow0 + r) * (3 * D_) + h * DH_ + j * 8;
        *(uint4*)((pl ? ql : qh) + r * AT_PAD + j * 8) = *(const uint4*)src;
    }
    __syncthreads();

    uint32_t qfh[2][4], qfl[2][4];
    {
        int row = w4 * 16 + (mi & 1) * 8 + ri;
#pragma unroll
        for (int ks = 0; ks < 2; ks++) {
            int col = ks * 16 + (mi >> 1) * 8;
            ldsm4(qfh[ks], sptr(qh + row * AT_PAD + col));
            ldsm4(qfl[ks], sptr(ql + row * AT_PAD + col));
        }
    }

    float cacc[4][4];
#pragma unroll
    for (int nt = 0; nt < 4; nt++)
#pragma unroll
        for (int e = 0; e < 4; e++) cacc[nt][e] = 0.f;
    float sr0 = 0.f, sr1 = 0.f;

    __half* mykv = kv + wg * 2 * AT_PLANE;

    for (int t = 0; t < 8; t++) {
        __syncthreads();
#pragma unroll
        for (int p = 0; p < 4; p++)
            *(uint4*)(kv + p * AT_PLANE + kr * AT_PAD + kj8) = prkv[p];
        __syncthreads();
        if (t + 1 < 8) {
#pragma unroll
            for (int p = 0; p < 4; p++) {
                int isv = p & 1;
                int colofs = (isv ? 2 * D_ : D_) + h * DH_ + kj8;
                size_t row = (size_t)(b * N_ + (2 * (t + 1) + (p >> 1)) * 64 + kr);
                prkv[p] = *(const uint4*)(qkvh + row * (3 * D_) + colofs);
            }
        }

        const __half* khp = mykv;
        const __half* vhp = mykv + AT_PLANE;

        // ---- phase 1: S = pq @ pk^T (q hi+lo) ----
        float sacc[8][4];
#pragma unroll
        for (int nt = 0; nt < 8; nt++)
#pragma unroll
            for (int e = 0; e < 4; e++) sacc[nt][e] = 0.f;

#pragma unroll
        for (int ks = 0; ks < 2; ks++) {
            int kb = ks * 16;
#pragma unroll
            for (int np = 0; np < 4; np++) {
                int rown = np * 16 + (mi >> 1) * 8 + ri;
                int coln = kb + (mi & 1) * 8;
                uint32_t bh[4];
                ldsm4(bh, sptr(khp + rown * AT_PAD + coln));
                mma16(sacc[np * 2 + 0], qfh[ks], bh[0], bh[1]);
                mma16(sacc[np * 2 + 0], qfl[ks], bh[0], bh[1]);
                mma16(sacc[np * 2 + 1], qfh[ks], bh[2], bh[3]);
                mma16(sacc[np * 2 + 1], qfl[ks], bh[2], bh[3]);
            }
        }
        // relu^2 + rowsum partials
#pragma unroll
        for (int nt = 0; nt < 8; nt++) {
#pragma unroll
            for (int e = 0; e < 4; e++) {
                float w = fmaxf(sacc[nt][e], 0.f);
                sacc[nt][e] = w * w;
            }
            sr0 += sacc[nt][0] + sacc[nt][1];
            sr1 += sacc[nt][2] + sacc[nt][3];
        }

        // ---- phase 2: C += P @ v (P hi only) ----
#pragma unroll
        for (int ks2 = 0; ks2 < 4; ks2++) {
            uint32_t ph[4];
            ph[0] = pack2h(__float2half_rn(sacc[2 * ks2][0]),
                           __float2half_rn(sacc[2 * ks2][1]));
            ph[1] = pack2h(__float2half_rn(sacc[2 * ks2][2]),
                           __float2half_rn(sacc[2 * ks2][3]));
            ph[2] = pack2h(__float2half_rn(sacc[2 * ks2 + 1][0]),
                           __float2half_rn(sacc[2 * ks2 + 1][1]));
            ph[3] = pack2h(__float2half_rn(sacc[2 * ks2 + 1][2]),
                           __float2half_rn(sacc[2 * ks2 + 1][3]));
            int rowv = ks2 * 16 + (mi & 1) * 8 + ri;
#pragma unroll
            for (int dp = 0; dp < 2; dp++) {
                int colv = (dp * 2 + (mi >> 1)) * 8;
                uint32_t bh[4];
                ldsm4t(bh, sptr(vhp + rowv * AT_PAD + colv));
                mma16(cacc[dp * 2 + 0], ph, bh[0], bh[1]);
                mma16(cacc[dp * 2 + 1], ph, bh[2], bh[3]);
            }
        }
    }

    __syncthreads();
    if (wg == 1) {
        float* cd = cred + (w4 * 32 + lane) * 16;
#pragma unroll
        for (int nt = 0; nt < 4; nt++)
#pragma unroll
            for (int e = 0; e < 4; e++) cd[nt * 4 + e] = cacc[nt][e];
        sred[(w4 * 32 + lane) * 2 + 0] = sr0;
        sred[(w4 * 32 + lane) * 2 + 1] = sr1;
    }
    __syncthreads();
    if (wg == 0) {
        const float* cd = cred + (w4 * 32 + lane) * 16;
#pragma unroll
        for (int nt = 0; nt < 4; nt++)
#pragma unroll
            for (int e = 0; e < 4; e++) cacc[nt][e] += cd[nt * 4 + e];
        sr0 += sred[(w4 * 32 + lane) * 2 + 0];
        sr1 += sred[(w4 * 32 + lane) * 2 + 1];
        sr0 += __shfl_xor_sync(0xffffffffu, sr0, 1);
        sr0 += __shfl_xor_sync(0xffffffffu, sr0, 2);
        sr1 += __shfl_xor_sync(0xffffffffu, sr1, 1);
        sr1 += __shfl_xor_sync(0xffffffffu, sr1, 2);
        float inv0 = 1.f / (sr0 + 1.f);
        float inv1 = 1.f / (sr1 + 1.f);

#pragma unroll
        for (int nt = 0; nt < 4; nt++)
#pragma unroll
            for (int e = 0; e < 4; e++) {
                int rl = w4 * 16 + g + ((e >> 1) ? 8 : 0);
                int dh = nt * 8 + 2 * tg + (e & 1);
                size_t row = qrow0 + rl;
                size_t vof = row * (3 * D_) + 2 * D_ + h * DH_ + dh;
                float vv = __half2float(qkvh[vof]) + __half2float(qkvl[vof]);
                float y = cacc[nt][e] * ((e >> 1) ? inv1 : inv0) - vv;
                __half hh, ll; split_hf(y, hh, ll);
                cmvh[row * D_ + h * DH_ + dh] = hh;
                cmvl[row * D_ + h * DH_ + dh] = ll;
            }
    }
}

// ---------------- silu-conv / halt ----------------
__global__ void siluconv_split(const float* __restrict__ gu, const float* __restrict__ cw,
                               int kidx, __half* __restrict__ oh,
                               __half* __restrict__ ol) {
    int idx = blockIdx.x * 256 + threadIdx.x;
    int i   = idx & (IN_ - 1);
    int bn  = idx >> 10;
    int n   = bn & (N_ - 1);
    const float* wp = cw + ((size_t)kidx * IN_ + i) * CK_;
    float gC = gu[(size_t)bn * (2 * IN_) + i];
    float uC = gu[(size_t)bn * (2 * IN_) + IN_ + i];
    float a = wp[1] * (gC / (1.f + expf(-gC)) * uC);
    if (n > 0) {
        float gm = gu[(size_t)(bn - 1) * (2 * IN_) + i];
        float um = gu[(size_t)(bn - 1) * (2 * IN_) + IN_ + i];
        a = fmaf(wp[0], gm / (1.f + expf(-gm)) * um, a);
    }
    if (n < N_ - 1) {
        float gp = gu[(size_t)(bn + 1) * (2 * IN_) + i];
        float up = gu[(size_t)(bn + 1) * (2 * IN_) + IN_ + i];
        a = fmaf(wp[2], gp / (1.f + expf(-gp)) * up, a);
    }
    __half hh, ll; split_hf(a, hh, ll);
    oh[idx] = hh;
    ol[idx] = ll;
}

__global__ void __launch_bounds__(256)
halt_dot(const float* __restrict__ qn, const float* __restrict__ hw, float* __restrict__ hd) {
    int row  = blockIdx.x * 8 + (threadIdx.x >> 5);
    int lane = threadIdx.x & 31;
    const float* ip = qn + (size_t)row * D_;
    float s = 0.f;
#pragma unroll
    for (int j = 0; j < 8; j++) s = fmaf(ip[j * 32 + lane], hw[j * 32 + lane], s);
    s = warpReduceSum(s);
    if (lane == 0) hd[row] = s;
}

__global__ void __launch_bounds__(1024)
halt_fin(const float* __restrict__ hd, const float* __restrict__ hb,
         float* __restrict__ out, int l4) {
    __shared__ float sh[32];
    int b = blockIdx.x;
    float v = hd[(size_t)b * N_ + threadIdx.x];
    v = warpReduceSum(v);
    if ((threadIdx.x & 31) == 0) sh[threadIdx.x >> 5] = v;
    __syncthreads();
    if (threadIdx.x < 32) {
        float t = sh[threadIdx.x];
        t = warpReduceSum(t);
        if (threadIdx.x == 0)
            out[l4 * B_ + b] = 1.f / (1.f + expf(-(t * (1.f / N_) + hb[0])));
    }
}

// ---------------- host orchestration ----------------
static inline void* symp(const void* sym) {
    void* p = nullptr;
    cudaGetSymbolAddress(&p, sym);
    return p;
}

extern "C" void kernel_launch(void* const* d_in, const int* in_sizes, int n_in,
                              void* d_out, int out_size) {
    const int*   ids   = (const int*)  d_in[0];
    const float* emb   = (const float*)d_in[1];
    const float* pos   = (const float*)d_in[2];
    const float* in_w  = (const float*)d_in[3];
    const float* in_b  = (const float*)d_in[4];
    const float* Wq    = (const float*)d_in[5];
    const float* Wk    = (const float*)d_in[6];
    const float* Wv    = (const float*)d_in[7];
    const float* Wo    = (const float*)d_in[8];
    const float* dts   = (const float*)d_in[9];
    const float* Wup   = (const float*)d_in[10];
    const float* cw    = (const float*)d_in[11];
    const float* Wd    = (const float*)d_in[12];
    const float* n1w   = (const float*)d_in[13];
    const float* n1b   = (const float*)d_in[14];
    const float* n2w   = (const float*)d_in[15];
    const float* n2b   = (const float*)d_in[16];
    const float* fin_w = (const float*)d_in[17];
    const float* fin_b = (const float*)d_in[18];
    const float* haltw = (const float*)d_in[19];
    const float* haltb = (const float*)d_in[20];
    const float* lm_w  = (const float*)d_in[21];

    float* out        = (float*)d_out;
    float* out_logits = out;
    float* out_halts  = out + (size_t)out_size - (size_t)(MAXL_ - TRUNC_) * B_;

    float* pX  = (float*)symp(g_X);
    float* pQ  = (float*)symp(g_Q);
    float* pGU = (float*)symp(g_gu);
    float* pQn0 = (float*)symp(g_qn);
    float* pHd0 = (float*)symp(g_hd);

    __half* pHcH = (__half*)symp(g_hc_h),  *pHcL = (__half*)symp(g_hc_l);
    __half* pQkH = (__half*)symp(g_qkv_h), *pQkL = (__half*)symp(g_qkv_l);
    __half* pCmH = (__half*)symp(g_cmv_h), *pCmL = (__half*)symp(g_cmv_l);
    __half* pHnH = (__half*)symp(g_hn_h),  *pHnL = (__half*)symp(g_hn_l);
    __half* pH2H = (__half*)symp(g_hc2_h), *pH2L = (__half*)symp(g_hc2_l);
    __half* pQnH0 = (__half*)symp(g_qn_h);

    __half* pWqH = (__half*)symp(g_wq_h);
    __half* pWkH = (__half*)symp(g_wk_h);
    __half* pWvH = (__half*)symp(g_wv_h);
    __half* pWoH = (__half*)symp(g_wo_h);
    __half* pWuH = (__half*)symp(g_wup_h);
    __half* pWdH = (__half*)symp(g_wd_h);
    __half* pLmH = (__half*)symp(g_lm_h);

    cudaFuncSetAttribute(gemm_bs<2>, cudaFuncAttributeMaxDynamicSharedMemorySize, GS_SMEM);
    cudaFuncSetAttribute(gemm_bs<3>, cudaFuncAttributeMaxDynamicSharedMemorySize, GS_SMEM);
    cudaFuncSetAttribute(gemm_bs<4>, cudaFuncAttributeMaxDynamicSharedMemorySize, GS_SMEM);
    cudaFuncSetAttribute(gemm_bw<1>, cudaFuncAttributeMaxDynamicSharedMemorySize, GW_SMEM);
    cudaFuncSetAttribute(gemm_bw<0>, cudaFuncAttributeMaxDynamicSharedMemorySize, GW_SMEM);
    cudaFuncSetAttribute(attn_bs,    cudaFuncAttributeMaxDynamicSharedMemorySize, AT_SMEM);

    const dim3 tb(32, 8);
    wsplit<<<dim3(8, 8, 4),    tb>>>(Wq,   pWqH, D_,  D_);
    wsplit<<<dim3(8, 8, 4),    tb>>>(Wk,   pWkH, D_,  D_);
    wsplit<<<dim3(8, 8, 4),    tb>>>(Wv,   pWvH, D_,  D_);
    wsplit<<<dim3(8, 8, 4),    tb>>>(Wo,   pWoH, D_,  D_);
    wsplit<<<dim3(64, 8, 4),   tb>>>(Wup,  pWuH, D_,  2 * IN_);
    wsplit<<<dim3(8, 32, 4),   tb>>>(Wd,   pWdH, IN_, D_);
    wsplit<<<dim3(1000, 8, 1), tb>>>(lm_w, pLmH, D_,  V_);

    embed_kernel<<<BN_, 256>>>(ids, emb, pos, pX);
    ln_kernel<<<BN_, 256>>>(pX, in_w, in_b, pX, pQ);

    const dim3 gQKV(12, BN_ / 64);
    const dim3 gDD(4, BN_ / 64);
    const dim3 gUP(2 * IN_ / 64, BN_ / 128);
    const dim3 gLM(V_ / 64, BN_ / 128);
    const dim3 gAT(B_ * H_, N_ / 64);
    const int  ec = (BN_ * IN_) / 256;
    const int  lnb = BN_ / 8;
    bool side_used = false;

    for (int l = 0; l < MAXL_; l++) {
        for (int k = 0; k < K_; k++) {
            size_t wo = (size_t)k * D_ * D_;
            ln_split<<<lnb, 256>>>(pQ, n1w + k * D_, n1b + k * D_, pX, pHcH, pHcL, nullptr);
            gemm_bs<4><<<gQKV, 256, GS_SMEM>>>(pHcH, pHcL,
                                               pWqH + wo, pWkH + wo, pWvH + wo,
                                               D_, 4, nullptr, 0,
                                               pQkH, pQkL, 3 * D_, nullptr, nullptr, 0);
            attn_bs<<<gAT, 256, AT_SMEM>>>(pQkH, pQkL, pCmH, pCmL);
            gemm_bs<2><<<gDD, 256, GS_SMEM>>>(pCmH, pCmL,
                                              pWoH + wo, pWoH + wo, pWoH + wo,
                                              D_, 4, pQ, D_,
                                              nullptr, nullptr, 0, pQ, dts, k);
            ln_split<<<lnb, 256>>>(pQ, n2w + k * D_, n2b + k * D_, nullptr, pHnH, pHnL, nullptr);
            size_t wu = (size_t)k * D_ * 2 * IN_;
            gemm_bw<1><<<gUP, 256, GW_SMEM>>>(pHnH, pHnL, pWuH + wu, D_, pGU, 2 * IN_);
            siluconv_split<<<ec, 256>>>(pGU, cw, k, pH2H, pH2L);
            size_t wd = (size_t)k * IN_ * D_;
            gemm_bs<3><<<gDD, 256, GS_SMEM>>>(pH2H, pH2L,
                                              pWdH + wd, pWdH + wd, pWdH + wd,
                                              IN_, 4, pQ, D_,
                                              nullptr, nullptr, 0, pQ, nullptr, 0);
        }
        if (l >= TRUNC_) {
            int l4 = l - TRUNC_;
            int pb = l4 & 1;
            float*  pQn  = pQn0  + (size_t)pb * BN_ * D_;
            float*  pHd  = pHd0  + (size_t)pb * BN_;
            __half* pQnH = pQnH0 + (size_t)pb * BN_ * D_;

            ln_split<<<lnb, 256>>>(pQ, fin_w, fin_b, nullptr, pQnH, nullptr, pQn);

            cudaEventRecord(g_sc.f, 0);
            cudaStreamWaitEvent(g_sc.s, g_sc.f, 0);
            halt_dot<<<lnb, 256, 0, g_sc.s>>>(pQn, haltw, pHd);
            halt_fin<<<B_, 1024, 0, g_sc.s>>>(pHd, haltb, out_halts, l4);
            gemm_bw<0><<<gLM, 256, GW_SMEM, g_sc.s>>>(pQnH, nullptr, pLmH,
                                                      D_, out_logits + (size_t)l4 * BN_ * V_, V_);
            side_used = true;
        }
    }

    if (side_used) {
        cudaEventRecord(g_sc.j, g_sc.s);
        cudaStreamWaitEvent(0, g_sc.j, 0);
    }
}

// round 17
// speedup vs baseline: 1.8020x; 1.0651x over previous
#include <cuda_runtime.h>
#include <cuda_fp16.h>
#include <math.h>
#include <stdint.h>

#define B_    2
#define N_    1024
#define D_    256
#define H_    8
#define DH_   32
#define K_    4
#define IN_   1024
#define V_    32000
#define CK_   3
#define MAXL_ 8
#define TRUNC_ 4
#define BN_   (B_ * N_)

// ---------------- fp32 scratch ----------------
__device__ float g_X [BN_ * D_];
__device__ float g_Q [BN_ * D_];
__device__ float g_gu[BN_ * 2 * IN_];
__device__ float g_qn[2][BN_ * D_];
__device__ float g_hd[2][BN_];

// ---------------- activation planes (fp16) ----------------
__device__ __align__(16) __half g_hc_h [BN_ * D_],     g_hc_l [BN_ * D_];
__device__ __align__(16) __half g_qkv_h[BN_ * 3 * D_], g_qkv_l[BN_ * 3 * D_];
__device__ __align__(16) __half g_cmv_h[BN_ * D_],     g_cmv_l[BN_ * D_];
__device__ __align__(16) __half g_hn_h [BN_ * D_];
__device__ __align__(16) __half g_hc2_h[BN_ * IN_],    g_hc2_l[BN_ * IN_];
__device__ __align__(16) __half g_qn_h [2][BN_ * D_];

// ---------------- transposed weights [n][k], fp16 hi only (B side) ----
__device__ __align__(16) __half g_wq_h [K_ * D_ * D_];
__device__ __align__(16) __half g_wk_h [K_ * D_ * D_];
__device__ __align__(16) __half g_wv_h [K_ * D_ * D_];
__device__ __align__(16) __half g_wo_h [K_ * D_ * D_];
__device__ __align__(16) __half g_wup_h[K_ * 2 * IN_ * D_];
__device__ __align__(16) __half g_wd_h [K_ * D_ * IN_];
__device__ __align__(16) __half g_lm_h [(size_t)V_ * D_];

// ---------------- side stream + events ----------------
struct SideCtx {
    cudaStream_t s;
    cudaEvent_t  f, j;
    SideCtx() {
        cudaStreamCreateWithFlags(&s, cudaStreamNonBlocking);
        cudaEventCreateWithFlags(&f, cudaEventDisableTiming);
        cudaEventCreateWithFlags(&j, cudaEventDisableTiming);
    }
};
static SideCtx g_sc;

// ---------------- helpers ----------------
__device__ __forceinline__ void split_hf(float v, __half& h, __half& l) {
    h = __float2half_rn(v);
    l = __float2half_rn(v - __half2float(h));
}
__device__ __forceinline__ uint32_t pack2h(__half a, __half b) {
    __half2 t = __halves2half2(a, b);
    return *reinterpret_cast<uint32_t*>(&t);
}
__device__ __forceinline__ uint32_t sptr(const void* p) {
    return (uint32_t)__cvta_generic_to_shared(p);
}
__device__ __forceinline__ void ldsm4(uint32_t* r, uint32_t sa) {
    asm volatile("ldmatrix.sync.aligned.m8n8.x4.shared.b16 {%0,%1,%2,%3}, [%4];"
                 : "=r"(r[0]), "=r"(r[1]), "=r"(r[2]), "=r"(r[3]) : "r"(sa));
}
__device__ __forceinline__ void ldsm4t(uint32_t* r, uint32_t sa) {
    asm volatile("ldmatrix.sync.aligned.m8n8.x4.trans.shared.b16 {%0,%1,%2,%3}, [%4];"
                 : "=r"(r[0]), "=r"(r[1]), "=r"(r[2]), "=r"(r[3]) : "r"(sa));
}
__device__ __forceinline__ void mma16(float* c, const uint32_t* a, uint32_t b0, uint32_t b1) {
    asm volatile("mma.sync.aligned.m16n8k16.row.col.f32.f16.f16.f32 "
                 "{%0,%1,%2,%3}, {%4,%5,%6,%7}, {%8,%9}, {%0,%1,%2,%3};"
                 : "+f"(c[0]), "+f"(c[1]), "+f"(c[2]), "+f"(c[3])
                 : "r"(a[0]), "r"(a[1]), "r"(a[2]), "r"(a[3]), "r"(b0), "r"(b1));
}
__device__ __forceinline__ float warpReduceSum(float v) {
#pragma unroll
    for (int o = 16; o > 0; o >>= 1) v += __shfl_xor_sync(0xffffffffu, v, o);
    return v;
}
__device__ __forceinline__ float blockReduceSum256(float v) {
    __shared__ float sh[8];
    int lane = threadIdx.x & 31;
    int wid  = threadIdx.x >> 5;
#pragma unroll
    for (int o = 16; o > 0; o >>= 1) v += __shfl_down_sync(0xffffffffu, v, o);
    __syncthreads();
    if (lane == 0) sh[wid] = v;
    __syncthreads();
    float t = 0.f;
#pragma unroll
    for (int i = 0; i < 8; i++) t += sh[i];
    return t;
}

// ---------------- weight transpose + fp16 quantize (hi only) ----------------
__global__ void wsplit(const float* __restrict__ W, __half* __restrict__ oh,
                       int Kd, int Nn)
{
    __shared__ float t[32][33];
    const float* Wz = W + (size_t)blockIdx.z * Kd * Nn;
    __half* ohz = oh + (size_t)blockIdx.z * Kd * Nn;
    int n0 = blockIdx.x * 32, k0 = blockIdx.y * 32;
    int tx = threadIdx.x, ty = threadIdx.y;
#pragma unroll
    for (int i = 0; i < 4; i++)
        t[ty + i * 8][tx] = Wz[(size_t)(k0 + ty + i * 8) * Nn + n0 + tx];
    __syncthreads();
#pragma unroll
    for (int i = 0; i < 4; i++) {
        int n = ty + i * 8;
        ohz[(size_t)(n0 + n) * Kd + k0 + tx] = __float2half_rn(t[tx][n]);
    }
}

// ---------------- embedding / LN ----------------
__global__ void embed_kernel(const int* __restrict__ ids, const float* __restrict__ emb,
                             const float* __restrict__ pos, float* __restrict__ X) {
    int row = blockIdx.x, d = threadIdx.x;
    int n = row & (N_ - 1);
    X[(size_t)row * D_ + d] = emb[(size_t)ids[row] * D_ + d] + pos[(size_t)n * D_ + d];
}

__global__ void ln_kernel(const float* __restrict__ in, const float* __restrict__ w,
                          const float* __restrict__ b, float* __restrict__ out,
                          float* __restrict__ out2) {
    int row = blockIdx.x, d = threadIdx.x;
    float x  = in[(size_t)row * D_ + d];
    float mu = blockReduceSum256(x) * (1.f / D_);
    float dx = x - mu;
    float var = blockReduceSum256(dx * dx) * (1.f / D_);
    float y = dx * rsqrtf(var + 1e-5f) * w[d] + b[d];
    out[(size_t)row * D_ + d] = y;
    if (out2) out2[(size_t)row * D_ + d] = y;
}

// ln -> split planes (ol optional), warp-per-row
__global__ void __launch_bounds__(256)
ln_split(const float* __restrict__ in, const float* __restrict__ w,
         const float* __restrict__ b, const float* __restrict__ addX,
         __half* __restrict__ oh, __half* __restrict__ ol,
         float* __restrict__ ofp) {
    int row  = blockIdx.x * 8 + (threadIdx.x >> 5);
    int lane = threadIdx.x & 31;
    const float* ip = in + (size_t)row * D_;
    float x[8], s = 0.f;
#pragma unroll
    for (int j = 0; j < 8; j++) { x[j] = ip[j * 32 + lane]; s += x[j]; }
    float mu = warpReduceSum(s) * (1.f / D_);
    float v = 0.f;
#pragma unroll
    for (int j = 0; j < 8; j++) { float dx = x[j] - mu; v += dx * dx; }
    float rs = rsqrtf(warpReduceSum(v) * (1.f / D_) + 1e-5f);
#pragma unroll
    for (int j = 0; j < 8; j++) {
        int d = j * 32 + lane;
        float y = (x[j] - mu) * rs * w[d] + b[d];
        if (addX) y += addX[(size_t)row * D_ + d];
        __half hh, ll; split_hf(y, hh, ll);
        oh[(size_t)row * D_ + d] = hh;
        if (ol) ol[(size_t)row * D_ + d] = ll;
        if (ofp) ofp[(size_t)row * D_ + d] = y;
    }
}

// ============================================================================
// gemm_bs: fp16x2 GEMM (A hi/lo planes, B hi plane), 64x64x64 tiles,
//   8 warps (2m x 4n), ldmatrix, register double-buffer.
// MODE: 0 fp32 store; 2 aux + softplus(dts[kidx])*x; 3 aux + x;
//       4 split-plane store (elu+1 when which<2)   [QKV]
// ============================================================================
#define GS_PAD  72
#define GS_SMEM (3 * 64 * GS_PAD * 2)

template <int MODE>
__global__ void __launch_bounds__(256)
gemm_bs(const __half* __restrict__ Agh, const __half* __restrict__ Agl,
        const __half* __restrict__ B0h, const __half* __restrict__ B1h,
        const __half* __restrict__ B2h,
        int Kd, int nblk,
        float* __restrict__ Cf, int ldc,
        __half* __restrict__ Oh, __half* __restrict__ Ol, int ldo,
        const float* __restrict__ aux, const float* __restrict__ dts, int kidx)
{
    extern __shared__ __half sm[];
    __half* Ash = sm;
    __half* Asl = Ash + 64 * GS_PAD;
    __half* Bsh = Asl + 64 * GS_PAD;

    const int tid  = threadIdx.x;
    const int lane = tid & 31, wid = tid >> 5;
    const int g = lane >> 2, tg = lane & 3;
    const int mi = lane >> 3, ri = lane & 7;
    const int wm = wid & 1, wn = wid >> 1;
    const int which = blockIdx.x / nblk;
    const int bxl   = blockIdx.x - which * nblk;
    const int col0  = bxl * 64;
    const int row0  = blockIdx.y * 64;
    const __half* Bgh = (which == 0) ? B0h : (which == 1) ? B1h : B2h;

    const int r0 = tid >> 3;
    const int c0 = (tid & 7) * 8;
    const __half* sA0 = Agh + (size_t)(row0 + r0) * Kd + c0;
    const __half* sA1 = Agl + (size_t)(row0 + r0) * Kd + c0;
    const __half* sB0 = Bgh + (size_t)(col0 + r0) * Kd + c0;
    const size_t rstep = (size_t)32 * Kd;

    float acc[2][2][4];
#pragma unroll
    for (int a = 0; a < 2; a++)
#pragma unroll
        for (int b = 0; b < 2; b++)
#pragma unroll
            for (int c = 0; c < 4; c++) acc[a][b][c] = 0.f;

    const int niter = Kd >> 6;
    uint4 pr[6];
    pr[0] = *(const uint4*)(sA0);
    pr[1] = *(const uint4*)(sA0 + rstep);
    pr[2] = *(const uint4*)(sA1);
    pr[3] = *(const uint4*)(sA1 + rstep);
    pr[4] = *(const uint4*)(sB0);
    pr[5] = *(const uint4*)(sB0 + rstep);

    for (int it2 = 0; it2 < niter; it2++) {
        __syncthreads();
        *(uint4*)(Ash + r0 * GS_PAD + c0)        = pr[0];
        *(uint4*)(Ash + (r0 + 32) * GS_PAD + c0) = pr[1];
        *(uint4*)(Asl + r0 * GS_PAD + c0)        = pr[2];
        *(uint4*)(Asl + (r0 + 32) * GS_PAD + c0) = pr[3];
        *(uint4*)(Bsh + r0 * GS_PAD + c0)        = pr[4];
        *(uint4*)(Bsh + (r0 + 32) * GS_PAD + c0) = pr[5];
        __syncthreads();
        if (it2 + 1 < niter) {
            int o = (it2 + 1) * 64;
            pr[0] = *(const uint4*)(sA0 + o);
            pr[1] = *(const uint4*)(sA0 + rstep + o);
            pr[2] = *(const uint4*)(sA1 + o);
            pr[3] = *(const uint4*)(sA1 + rstep + o);
            pr[4] = *(const uint4*)(sB0 + o);
            pr[5] = *(const uint4*)(sB0 + rstep + o);
        }

#pragma unroll
        for (int ks = 0; ks < 4; ks++) {
            int kb = ks * 16;
            uint32_t ah[2][4], al[2][4];
#pragma unroll
            for (int mt = 0; mt < 2; mt++) {
                int row = wm * 32 + mt * 16 + (mi & 1) * 8 + ri;
                int col = kb + (mi >> 1) * 8;
                ldsm4(ah[mt], sptr(Ash + row * GS_PAD + col));
                ldsm4(al[mt], sptr(Asl + row * GS_PAD + col));
            }
            int rowb = wn * 16 + (mi >> 1) * 8 + ri;
            int colb = kb + (mi & 1) * 8;
            uint32_t bh[4];
            ldsm4(bh, sptr(Bsh + rowb * GS_PAD + colb));
#pragma unroll
            for (int nt = 0; nt < 2; nt++)
#pragma unroll
                for (int mt = 0; mt < 2; mt++) {
                    mma16(acc[mt][nt], ah[mt], bh[2 * nt], bh[2 * nt + 1]);
                    mma16(acc[mt][nt], al[mt], bh[2 * nt], bh[2 * nt + 1]);
                }
        }
    }

    float sp = 0.f;
    if (MODE == 2) sp = log1pf(expf(dts[kidx]));
    const int ocolbase = which * (nblk * 64) + col0;
#pragma unroll
    for (int mt = 0; mt < 2; mt++)
#pragma unroll
        for (int nt = 0; nt < 2; nt++)
#pragma unroll
            for (int e = 0; e < 4; e++) {
                int r = row0 + wm * 32 + mt * 16 + g + ((e >> 1) ? 8 : 0);
                int c = ocolbase + wn * 16 + nt * 8 + 2 * tg + (e & 1);
                float x = acc[mt][nt][e];
                if (MODE == 4) {
                    float y = (which < 2) ? ((x > 0.f) ? (x + 1.f) : expf(x)) : x;
                    __half hh, ll; split_hf(y, hh, ll);
                    Oh[(size_t)r * ldo + c] = hh;
                    Ol[(size_t)r * ldo + c] = ll;
                } else {
                    size_t o = (size_t)r * ldc + c;
                    if (MODE == 2)      Cf[o] = aux[o] + sp * x;
                    else if (MODE == 3) Cf[o] = aux[o] + x;
                    else                Cf[o] = x;
                }
            }
}

// ============================================================================
// gemm_bw: wide-tile GEMM, 128x64 tiles, fp32 out.
//   ALO=1: A hi+lo (fp16x2);  ALO=0: A hi only (fp16x1; Wup + LM head).
// ============================================================================
#define GW_PAD  72
#define GW_SMEM ((2 * 128 + 64) * GW_PAD * 2)

template <int ALO>
__global__ void __launch_bounds__(256)
gemm_bw(const __half* __restrict__ Agh, const __half* __restrict__ Agl,
        const __half* __restrict__ Bgh,
        int Kd, float* __restrict__ Cf, int ldc)
{
    extern __shared__ __half sm[];
    __half* Ash = sm;
    __half* Asl = Ash + 128 * GW_PAD;
    __half* Bsh = Asl + (ALO ? 128 * GW_PAD : 0);

    const int tid  = threadIdx.x;
    const int lane = tid & 31, wid = tid >> 5;
    const int g = lane >> 2, tg = lane & 3;
    const int mi = lane >> 3, ri = lane & 7;
    const int wm = wid & 3, wn = wid >> 2;
    const int col0 = blockIdx.x * 64;
    const int row0 = blockIdx.y * 128;

    float acc[2][4][4];
#pragma unroll
    for (int a = 0; a < 2; a++)
#pragma unroll
        for (int b = 0; b < 4; b++)
#pragma unroll
            for (int c = 0; c < 4; c++) acc[a][b][c] = 0.f;

    for (int kt = 0; kt < Kd; kt += 64) {
        __syncthreads();
#pragma unroll
        for (int it = 0; it < (ALO ? 8 : 4); it++) {
            int f  = it * 256 + tid;
            int pl = ALO ? (f >> 10) : 0;
            int r  = (f >> 3) & 127;
            int c8 = (f & 7) * 8;
            __half* dst = (pl ? Asl : Ash) + r * GW_PAD + c8;
            const __half* src = (pl ? Agl : Agh) + (size_t)(row0 + r) * Kd + kt + c8;
            *(uint4*)dst = *(const uint4*)src;
        }
#pragma unroll
        for (int it = 0; it < 2; it++) {
            int f  = it * 256 + tid;
            int r  = f >> 3;
            int c8 = (f & 7) * 8;
            *(uint4*)(Bsh + r * GW_PAD + c8) =
                *(const uint4*)(Bgh + (size_t)(col0 + r) * Kd + kt + c8);
        }
        __syncthreads();

#pragma unroll
        for (int ks = 0; ks < 4; ks++) {
            int kb = ks * 16;
            uint32_t ah[2][4], al[2][4];
#pragma unroll
            for (int mt = 0; mt < 2; mt++) {
                int row = wm * 32 + mt * 16 + (mi & 1) * 8 + ri;
                int col = kb + (mi >> 1) * 8;
                ldsm4(ah[mt], sptr(Ash + row * GW_PAD + col));
                if (ALO) ldsm4(al[mt], sptr(Asl + row * GW_PAD + col));
            }
            uint32_t bh[2][4];
#pragma unroll
            for (int np = 0; np < 2; np++) {
                int rowb = wn * 32 + np * 16 + (mi >> 1) * 8 + ri;
                int colb = kb + (mi & 1) * 8;
                ldsm4(bh[np], sptr(Bsh + rowb * GW_PAD + colb));
            }
#pragma unroll
            for (int np = 0; np < 2; np++)
#pragma unroll
                for (int sub = 0; sub < 2; sub++) {
                    int nt = np * 2 + sub;
#pragma unroll
                    for (int mt = 0; mt < 2; mt++) {
                        mma16(acc[mt][nt], ah[mt], bh[np][2 * sub], bh[np][2 * sub + 1]);
                        if (ALO) mma16(acc[mt][nt], al[mt], bh[np][2 * sub], bh[np][2 * sub + 1]);
                    }
                }
        }
    }

#pragma unroll
    for (int mt = 0; mt < 2; mt++)
#pragma unroll
        for (int nt = 0; nt < 4; nt++)
#pragma unroll
            for (int e = 0; e < 4; e++) {
                int r = row0 + wm * 32 + mt * 16 + g + ((e >> 1) ? 8 : 0);
                int c = col0 + wn * 32 + nt * 8 + 2 * tg + (e & 1);
                Cf[(size_t)r * ldc + c] = acc[mt][nt][e];
            }
}

// ============================================================================
// attn_bs: flash-style, fully fp16x1 (q hi, k hi, P hi, v hi).
// ============================================================================
#define AT_PAD   40
#define AT_PLANE (64 * AT_PAD)
#define AT_SMEM  ((1 + 4) * AT_PLANE * 2 + (4 * 32 * 16 + 4 * 32 * 2) * 4)

__global__ void __launch_bounds__(256)
attn_bs(const __half* __restrict__ qkvh, const __half* __restrict__ qkvl,
        __half* __restrict__ cmvh, __half* __restrict__ cmvl)
{
    extern __shared__ __half smb[];
    __half* qh = smb;
    __half* kv = qh + AT_PLANE;                 // 4 planes: [t0:kh,vh][t1:kh,vh]
    float* cred = (float*)(kv + 4 * AT_PLANE);  // [128][16]
    float* sred = cred + 4 * 32 * 16;           // [128][2]

    const int tid  = threadIdx.x;
    const int lane = tid & 31, wid = tid >> 5;
    const int w4 = wid & 3, wg = wid >> 2;
    const int g = lane >> 2, tg = lane & 3;
    const int mi = lane >> 3, ri = lane & 7;
    const int b = blockIdx.x >> 3, h = blockIdx.x & 7;
    const int qb = blockIdx.y;
    const size_t qrow0 = (size_t)(b * N_ + qb * 64);

    const int kr  = tid >> 2;
    const int kj8 = (tid & 3) * 8;

    uint4 prkv[4];
#pragma unroll
    for (int p = 0; p < 4; p++) {
        int isv = p & 1;
        int colofs = (isv ? 2 * D_ : D_) + h * DH_ + kj8;
        size_t row = (size_t)(b * N_ + (p >> 1) * 64 + kr);
        prkv[p] = *(const uint4*)(qkvh + row * (3 * D_) + colofs);
    }

    // stage q hi plane (256 uint4, one per thread)
    {
        int r = tid >> 2;
        int j = tid & 3;
        const __half* src = qkvh + (qrow0 + r) * (3 * D_) + h * DH_ + j * 8;
        *(uint4*)(qh + r * AT_PAD + j * 8) = *(const uint4*)src;
    }
    __syncthreads();

    uint32_t qfh[2][4];
    {
        int row = w4 * 16 + (mi & 1) * 8 + ri;
#pragma unroll
        for (int ks = 0; ks < 2; ks++) {
            int col = ks * 16 + (mi >> 1) * 8;
            ldsm4(qfh[ks], sptr(qh + row * AT_PAD + col));
        }
    }

    float cacc[4][4];
#pragma unroll
    for (int nt = 0; nt < 4; nt++)
#pragma unroll
        for (int e = 0; e < 4; e++) cacc[nt][e] = 0.f;
    float sr0 = 0.f, sr1 = 0.f;

    __half* mykv = kv + wg * 2 * AT_PLANE;

    for (int t = 0; t < 8; t++) {
        __syncthreads();
#pragma unroll
        for (int p = 0; p < 4; p++)
            *(uint4*)(kv + p * AT_PLANE + kr * AT_PAD + kj8) = prkv[p];
        __syncthreads();
        if (t + 1 < 8) {
#pragma unroll
            for (int p = 0; p < 4; p++) {
                int isv = p & 1;
                int colofs = (isv ? 2 * D_ : D_) + h * DH_ + kj8;
                size_t row = (size_t)(b * N_ + (2 * (t + 1) + (p >> 1)) * 64 + kr);
                prkv[p] = *(const uint4*)(qkvh + row * (3 * D_) + colofs);
            }
        }

        const __half* khp = mykv;
        const __half* vhp = mykv + AT_PLANE;

        // ---- phase 1: S = pq @ pk^T (q hi only) ----
        float sacc[8][4];
#pragma unroll
        for (int nt = 0; nt < 8; nt++)
#pragma unroll
            for (int e = 0; e < 4; e++) sacc[nt][e] = 0.f;

#pragma unroll
        for (int ks = 0; ks < 2; ks++) {
            int kb = ks * 16;
#pragma unroll
            for (int np = 0; np < 4; np++) {
                int rown = np * 16 + (mi >> 1) * 8 + ri;
                int coln = kb + (mi & 1) * 8;
                uint32_t bh[4];
                ldsm4(bh, sptr(khp + rown * AT_PAD + coln));
                mma16(sacc[np * 2 + 0], qfh[ks], bh[0], bh[1]);
                mma16(sacc[np * 2 + 1], qfh[ks], bh[2], bh[3]);
            }
        }
        // relu^2 + rowsum partials
#pragma unroll
        for (int nt = 0; nt < 8; nt++) {
#pragma unroll
            for (int e = 0; e < 4; e++) {
                float w = fmaxf(sacc[nt][e], 0.f);
                sacc[nt][e] = w * w;
            }
            sr0 += sacc[nt][0] + sacc[nt][1];
            sr1 += sacc[nt][2] + sacc[nt][3];
        }

        // ---- phase 2: C += P @ v (P hi only) ----
#pragma unroll
        for (int ks2 = 0; ks2 < 4; ks2++) {
            uint32_t ph[4];
            ph[0] = pack2h(__float2half_rn(sacc[2 * ks2][0]),
                           __float2half_rn(sacc[2 * ks2][1]));
            ph[1] = pack2h(__float2half_rn(sacc[2 * ks2][2]),
                           __float2half_rn(sacc[2 * ks2][3]));
            ph[2] = pack2h(__float2half_rn(sacc[2 * ks2 + 1][0]),
                           __float2half_rn(sacc[2 * ks2 + 1][1]));
            ph[3] = pack2h(__float2half_rn(sacc[2 * ks2 + 1][2]),
                           __float2half_rn(sacc[2 * ks2 + 1][3]));
            int rowv = ks2 * 16 + (mi & 1) * 8 + ri;
#pragma unroll
            for (int dp = 0; dp < 2; dp++) {
                int colv = (dp * 2 + (mi >> 1)) * 8;
                uint32_t bh[4];
                ldsm4t(bh, sptr(vhp + rowv * AT_PAD + colv));
                mma16(cacc[dp * 2 + 0], ph, bh[0], bh[1]);
                mma16(cacc[dp * 2 + 1], ph, bh[2], bh[3]);
            }
        }
    }

    __syncthreads();
    if (wg == 1) {
        float* cd = cred + (w4 * 32 + lane) * 16;
#pragma unroll
        for (int nt = 0; nt < 4; nt++)
#pragma unroll
            for (int e = 0; e < 4; e++) cd[nt * 4 + e] = cacc[nt][e];
        sred[(w4 * 32 + lane) * 2 + 0] = sr0;
        sred[(w4 * 32 + lane) * 2 + 1] = sr1;
    }
    __syncthreads();
    if (wg == 0) {
        const float* cd = cred + (w4 * 32 + lane) * 16;
#pragma unroll
        for (int nt = 0; nt < 4; nt++)
#pragma unroll
            for (int e = 0; e < 4; e++) cacc[nt][e] += cd[nt * 4 + e];
        sr0 += sred[(w4 * 32 + lane) * 2 + 0];
        sr1 += sred[(w4 * 32 + lane) * 2 + 1];
        sr0 += __shfl_xor_sync(0xffffffffu, sr0, 1);
        sr0 += __shfl_xor_sync(0xffffffffu, sr0, 2);
        sr1 += __shfl_xor_sync(0xffffffffu, sr1, 1);
        sr1 += __shfl_xor_sync(0xffffffffu, sr1, 2);
        float inv0 = 1.f / (sr0 + 1.f);
        float inv1 = 1.f / (sr1 + 1.f);

#pragma unroll
        for (int nt = 0; nt < 4; nt++)
#pragma unroll
            for (int e = 0; e < 4; e++) {
                int rl = w4 * 16 + g + ((e >> 1) ? 8 : 0);
                int dh = nt * 8 + 2 * tg + (e & 1);
                size_t row = qrow0 + rl;
                size_t vof = row * (3 * D_) + 2 * D_ + h * DH_ + dh;
                float vv = __half2float(qkvh[vof]) + __half2float(qkvl[vof]);
                float y = cacc[nt][e] * ((e >> 1) ? inv1 : inv0) - vv;
                __half hh, ll; split_hf(y, hh, ll);
                cmvh[row * D_ + h * DH_ + dh] = hh;
                cmvl[row * D_ + h * DH_ + dh] = ll;
            }
    }
}

// ---------------- silu-conv / halt ----------------
__global__ void siluconv_split(const float* __restrict__ gu, const float* __restrict__ cw,
                               int kidx, __half* __restrict__ oh,
                               __half* __restrict__ ol) {
    int idx = blockIdx.x * 256 + threadIdx.x;
    int i   = idx & (IN_ - 1);
    int bn  = idx >> 10;
    int n   = bn & (N_ - 1);
    const float* wp = cw + ((size_t)kidx * IN_ + i) * CK_;
    float gC = gu[(size_t)bn * (2 * IN_) + i];
    float uC = gu[(size_t)bn * (2 * IN_) + IN_ + i];
    float a = wp[1] * (gC / (1.f + expf(-gC)) * uC);
    if (n > 0) {
        float gm = gu[(size_t)(bn - 1) * (2 * IN_) + i];
        float um = gu[(size_t)(bn - 1) * (2 * IN_) + IN_ + i];
        a = fmaf(wp[0], gm / (1.f + expf(-gm)) * um, a);
    }
    if (n < N_ - 1) {
        float gp = gu[(size_t)(bn + 1) * (2 * IN_) + i];
        float up = gu[(size_t)(bn + 1) * (2 * IN_) + IN_ + i];
        a = fmaf(wp[2], gp / (1.f + expf(-gp)) * up, a);
    }
    __half hh, ll; split_hf(a, hh, ll);
    oh[idx] = hh;
    ol[idx] = ll;
}

__global__ void __launch_bounds__(256)
halt_dot(const float* __restrict__ qn, const float* __restrict__ hw, float* __restrict__ hd) {
    int row  = blockIdx.x * 8 + (threadIdx.x >> 5);
    int lane = threadIdx.x & 31;
    const float* ip = qn + (size_t)row * D_;
    float s = 0.f;
#pragma unroll
    for (int j = 0; j < 8; j++) s = fmaf(ip[j * 32 + lane], hw[j * 32 + lane], s);
    s = warpReduceSum(s);
    if (lane == 0) hd[row] = s;
}

__global__ void __launch_bounds__(1024)
halt_fin(const float* __restrict__ hd, const float* __restrict__ hb,
         float* __restrict__ out, int l4) {
    __shared__ float sh[32];
    int b = blockIdx.x;
    float v = hd[(size_t)b * N_ + threadIdx.x];
    v = warpReduceSum(v);
    if ((threadIdx.x & 31) == 0) sh[threadIdx.x >> 5] = v;
    __syncthreads();
    if (threadIdx.x < 32) {
        float t = sh[threadIdx.x];
        t = warpReduceSum(t);
        if (threadIdx.x == 0)
            out[l4 * B_ + b] = 1.f / (1.f + expf(-(t * (1.f / N_) + hb[0])));
    }
}

// ---------------- host orchestration ----------------
static inline void* symp(const void* sym) {
    void* p = nullptr;
    cudaGetSymbolAddress(&p, sym);
    return p;
}

extern "C" void kernel_launch(void* const* d_in, const int* in_sizes, int n_in,
                              void* d_out, int out_size) {
    const int*   ids   = (const int*)  d_in[0];
    const float* emb   = (const float*)d_in[1];
    const float* pos   = (const float*)d_in[2];
    const float* in_w  = (const float*)d_in[3];
    const float* in_b  = (const float*)d_in[4];
    const float* Wq    = (const float*)d_in[5];
    const float* Wk    = (const float*)d_in[6];
    const float* Wv    = (const float*)d_in[7];
    const float* Wo    = (const float*)d_in[8];
    const float* dts   = (const float*)d_in[9];
    const float* Wup   = (const float*)d_in[10];
    const float* cw    = (const float*)d_in[11];
    const float* Wd    = (const float*)d_in[12];
    const float* n1w   = (const float*)d_in[13];
    const float* n1b   = (const float*)d_in[14];
    const float* n2w   = (const float*)d_in[15];
    const float* n2b   = (const float*)d_in[16];
    const float* fin_w = (const float*)d_in[17];
    const float* fin_b = (const float*)d_in[18];
    const float* haltw = (const float*)d_in[19];
    const float* haltb = (const float*)d_in[20];
    const float* lm_w  = (const float*)d_in[21];

    float* out        = (float*)d_out;
    float* out_logits = out;
    float* out_halts  = out + (size_t)out_size - (size_t)(MAXL_ - TRUNC_) * B_;

    float* pX  = (float*)symp(g_X);
    float* pQ  = (float*)symp(g_Q);
    float* pGU = (float*)symp(g_gu);
    float* pQn0 = (float*)symp(g_qn);
    float* pHd0 = (float*)symp(g_hd);

    __half* pHcH = (__half*)symp(g_hc_h),  *pHcL = (__half*)symp(g_hc_l);
    __half* pQkH = (__half*)symp(g_qkv_h), *pQkL = (__half*)symp(g_qkv_l);
    __half* pCmH = (__half*)symp(g_cmv_h), *pCmL = (__half*)symp(g_cmv_l);
    __half* pHnH = (__half*)symp(g_hn_h);
    __half* pH2H = (__half*)symp(g_hc2_h), *pH2L = (__half*)symp(g_hc2_l);
    __half* pQnH0 = (__half*)symp(g_qn_h);

    __half* pWqH = (__half*)symp(g_wq_h);
    __half* pWkH = (__half*)symp(g_wk_h);
    __half* pWvH = (__half*)symp(g_wv_h);
    __half* pWoH = (__half*)symp(g_wo_h);
    __half* pWuH = (__half*)symp(g_wup_h);
    __half* pWdH = (__half*)symp(g_wd_h);
    __half* pLmH = (__half*)symp(g_lm_h);

    cudaFuncSetAttribute(gemm_bs<2>, cudaFuncAttributeMaxDynamicSharedMemorySize, GS_SMEM);
    cudaFuncSetAttribute(gemm_bs<3>, cudaFuncAttributeMaxDynamicSharedMemorySize, GS_SMEM);
    cudaFuncSetAttribute(gemm_bs<4>, cudaFuncAttributeMaxDynamicSharedMemorySize, GS_SMEM);
    cudaFuncSetAttribute(gemm_bw<1>, cudaFuncAttributeMaxDynamicSharedMemorySize, GW_SMEM);
    cudaFuncSetAttribute(gemm_bw<0>, cudaFuncAttributeMaxDynamicSharedMemorySize, GW_SMEM);
    cudaFuncSetAttribute(attn_bs,    cudaFuncAttributeMaxDynamicSharedMemorySize, AT_SMEM);

    const dim3 tb(32, 8);
    wsplit<<<dim3(8, 8, 4),    tb>>>(Wq,   pWqH, D_,  D_);
    wsplit<<<dim3(8, 8, 4),    tb>>>(Wk,   pWkH, D_,  D_);
    wsplit<<<dim3(8, 8, 4),    tb>>>(Wv,   pWvH, D_,  D_);
    wsplit<<<dim3(8, 8, 4),    tb>>>(Wo,   pWoH, D_,  D_);
    wsplit<<<dim3(64, 8, 4),   tb>>>(Wup,  pWuH, D_,  2 * IN_);
    wsplit<<<dim3(8, 32, 4),   tb>>>(Wd,   pWdH, IN_, D_);
    wsplit<<<dim3(1000, 8, 1), tb>>>(lm_w, pLmH, D_,  V_);

    embed_kernel<<<BN_, 256>>>(ids, emb, pos, pX);
    ln_kernel<<<BN_, 256>>>(pX, in_w, in_b, pX, pQ);

    const dim3 gQKV(12, BN_ / 64);
    const dim3 gDD(4, BN_ / 64);
    const dim3 gUP(2 * IN_ / 64, BN_ / 128);
    const dim3 gLM(V_ / 64, BN_ / 128);
    const dim3 gAT(B_ * H_, N_ / 64);
    const int  ec = (BN_ * IN_) / 256;
    const int  lnb = BN_ / 8;
    bool side_used = false;

    for (int l = 0; l < MAXL_; l++) {
        for (int k = 0; k < K_; k++) {
            size_t wo = (size_t)k * D_ * D_;
            ln_split<<<lnb, 256>>>(pQ, n1w + k * D_, n1b + k * D_, pX, pHcH, pHcL, nullptr);
            gemm_bs<4><<<gQKV, 256, GS_SMEM>>>(pHcH, pHcL,
                                               pWqH + wo, pWkH + wo, pWvH + wo,
                                               D_, 4, nullptr, 0,
                                               pQkH, pQkL, 3 * D_, nullptr, nullptr, 0);
            attn_bs<<<gAT, 256, AT_SMEM>>>(pQkH, pQkL, pCmH, pCmL);
            gemm_bs<2><<<gDD, 256, GS_SMEM>>>(pCmH, pCmL,
                                              pWoH + wo, pWoH + wo, pWoH + wo,
                                              D_, 4, pQ, D_,
                                              nullptr, nullptr, 0, pQ, dts, k);
            ln_split<<<lnb, 256>>>(pQ, n2w + k * D_, n2b + k * D_, nullptr, pHnH, nullptr, nullptr);
            size_t wu = (size_t)k * D_ * 2 * IN_;
            gemm_bw<0><<<gUP, 256, GW_SMEM>>>(pHnH, nullptr, pWuH + wu, D_, pGU, 2 * IN_);
            siluconv_split<<<ec, 256>>>(pGU, cw, k, pH2H, pH2L);
            size_t wd = (size_t)k * IN_ * D_;
            gemm_bs<3><<<gDD, 256, GS_SMEM>>>(pH2H, pH2L,
                                              pWdH + wd, pWdH + wd, pWdH + wd,
                                              IN_, 4, pQ, D_,
                                              nullptr, nullptr, 0, pQ, nullptr, 0);
        }
        if (l >= TRUNC_) {
            int l4 = l - TRUNC_;
            int pb = l4 & 1;
            float*  pQn  = pQn0  + (size_t)pb * BN_ * D_;
            float*  pHd  = pHd0  + (size_t)pb * BN_;
            __half* pQnH = pQnH0 + (size_t)pb * BN_ * D_;

            ln_split<<<lnb, 256>>>(pQ, fin_w, fin_b, nullptr, pQnH, nullptr, pQn);

            cudaEventRecord(g_sc.f, 0);
            cudaStreamWaitEvent(g_sc.s, g_sc.f, 0);
            halt_dot<<<lnb, 256, 0, g_sc.s>>>(pQn, haltw, pHd);
            halt_fin<<<B_, 1024, 0, g_sc.s>>>(pHd, haltb, out_halts, l4);
            gemm_bw<0><<<gLM, 256, GW_SMEM, g_sc.s>>>(pQnH, nullptr, pLmH,
                                                      D_, out_logits + (size_t)l4 * BN_ * V_, V_);
            side_used = true;
        }
    }

    if (side_used) {
        cudaEventRecord(g_sc.j, g_sc.s);
        cudaStreamWaitEvent(0, g_sc.j, 0);
    }
}